// round 2
// baseline (speedup 1.0000x reference)
#include <cuda_runtime.h>
#include <math.h>

// Problem shape (fixed by the reference): N=4, T=4096, D=Q=V=1024.
#define NBATCH 4
#define SEQ    4096
#define DIM    1024

// Scratch: q,k,v (64 MB each) + scores (256 MB). Static __device__ arrays
// (allocation inside kernel_launch is forbidden).
__device__ float g_q[(size_t)NBATCH * SEQ * DIM];
__device__ float g_k[(size_t)NBATCH * SEQ * DIM];
__device__ float g_v[(size_t)NBATCH * SEQ * DIM];
__device__ float g_s[(size_t)NBATCH * SEQ * SEQ];

// ---------------------------------------------------------------------------
// Classic 128x128x16 SGEMM, 256 threads, 8x8 register tile per thread.
//   C[m][n] = alpha * sum_k A[m][k] * op(B)[k][n]  (+ bias[n])
// B_KMAJOR=true : B stored [N][K] row-major (i.e. C = A * B^T)   -- X*W^T, Q*K^T
// B_KMAJOR=false: B stored [K][N] row-major (i.e. C = A * B)     -- Attn*V
// All dims here are multiples of the tile sizes, so no bounds checks.
// ---------------------------------------------------------------------------
constexpr int BM = 128, BN = 128, BK = 16, TM = 8, TN = 8;

template <bool B_KMAJOR, bool HAS_BIAS>
__global__ void __launch_bounds__(256)
sgemm_kernel(const float* __restrict__ Ab, const float* __restrict__ Bb,
             const float* __restrict__ bias, float* __restrict__ Cb,
             int M, int N, int K,
             size_t strideA, size_t strideB, size_t strideC, float alpha)
{
    const float* A = Ab + (size_t)blockIdx.z * strideA;
    const float* B = Bb + (size_t)blockIdx.z * strideB;
    float*       C = Cb + (size_t)blockIdx.z * strideC;

    __shared__ float As[BK][BM];
    __shared__ float Bs[BK][BN];

    const int tid = threadIdx.x;
    const int tx  = tid & 15;        // 16 thread columns
    const int ty  = tid >> 4;        // 16 thread rows
    const int m0  = blockIdx.y * BM;
    const int n0  = blockIdx.x * BN;

    float acc[TM][TN];
#pragma unroll
    for (int i = 0; i < TM; i++)
#pragma unroll
        for (int j = 0; j < TN; j++) acc[i][j] = 0.0f;

    for (int k0 = 0; k0 < K; k0 += BK) {
        // --- load A tile (BM x BK), stored transposed in shared ---
#pragma unroll
        for (int l = 0; l < 2; l++) {
            int v   = tid + 256 * l;          // 512 float4 loads total
            int row = v >> 2;                 // 0..127
            int c4  = (v & 3) * 4;            // 0,4,8,12
            float4 a = *reinterpret_cast<const float4*>(
                &A[(size_t)(m0 + row) * K + k0 + c4]);
            As[c4 + 0][row] = a.x;
            As[c4 + 1][row] = a.y;
            As[c4 + 2][row] = a.z;
            As[c4 + 3][row] = a.w;
        }
        // --- load B tile ---
        if (B_KMAJOR) {
#pragma unroll
            for (int l = 0; l < 2; l++) {
                int v   = tid + 256 * l;
                int row = v >> 2;             // n-index within tile
                int c4  = (v & 3) * 4;        // k-offset
                float4 b = *reinterpret_cast<const float4*>(
                    &B[(size_t)(n0 + row) * K + k0 + c4]);
                Bs[c4 + 0][row] = b.x;
                Bs[c4 + 1][row] = b.y;
                Bs[c4 + 2][row] = b.z;
                Bs[c4 + 3][row] = b.w;
            }
        } else {
#pragma unroll
            for (int l = 0; l < 2; l++) {
                int v   = tid + 256 * l;
                int row = v >> 5;             // 0..15 (k within tile)
                int c4  = (v & 31) * 4;       // 0..124 (n within tile)
                *reinterpret_cast<float4*>(&Bs[row][c4]) =
                    *reinterpret_cast<const float4*>(
                        &B[(size_t)(k0 + row) * N + n0 + c4]);
            }
        }
        __syncthreads();

        // --- FMA over this K-slab ---
#pragma unroll
        for (int kk = 0; kk < BK; kk++) {
            float a[TM], b[TN];
            *reinterpret_cast<float4*>(&a[0]) =
                *reinterpret_cast<const float4*>(&As[kk][ty * TM]);
            *reinterpret_cast<float4*>(&a[4]) =
                *reinterpret_cast<const float4*>(&As[kk][ty * TM + 4]);
            *reinterpret_cast<float4*>(&b[0]) =
                *reinterpret_cast<const float4*>(&Bs[kk][tx * TN]);
            *reinterpret_cast<float4*>(&b[4]) =
                *reinterpret_cast<const float4*>(&Bs[kk][tx * TN + 4]);
#pragma unroll
            for (int i = 0; i < TM; i++)
#pragma unroll
                for (int j = 0; j < TN; j++)
                    acc[i][j] = fmaf(a[i], b[j], acc[i][j]);
        }
        __syncthreads();
    }

    // --- epilogue: alpha scale + optional bias, vectorized stores ---
    float bcol[TN];
#pragma unroll
    for (int j = 0; j < TN; j++)
        bcol[j] = HAS_BIAS ? bias[n0 + tx * TN + j] : 0.0f;

#pragma unroll
    for (int i = 0; i < TM; i++) {
        float* cp = &C[(size_t)(m0 + ty * TM + i) * N + n0 + tx * TN];
        float4 r0, r1;
        r0.x = fmaf(alpha, acc[i][0], bcol[0]);
        r0.y = fmaf(alpha, acc[i][1], bcol[1]);
        r0.z = fmaf(alpha, acc[i][2], bcol[2]);
        r0.w = fmaf(alpha, acc[i][3], bcol[3]);
        r1.x = fmaf(alpha, acc[i][4], bcol[4]);
        r1.y = fmaf(alpha, acc[i][5], bcol[5]);
        r1.z = fmaf(alpha, acc[i][6], bcol[6]);
        r1.w = fmaf(alpha, acc[i][7], bcol[7]);
        *reinterpret_cast<float4*>(cp)     = r0;
        *reinterpret_cast<float4*>(cp + 4) = r1;
    }
}

// ---------------------------------------------------------------------------
// Row softmax over 4096-wide rows. One block (256 threads) per row,
// 16 elements per thread, in registers.
// ---------------------------------------------------------------------------
__global__ void __launch_bounds__(256) softmax_kernel(float* __restrict__ S)
{
    float* p = S + (size_t)blockIdx.x * SEQ;
    const int t = threadIdx.x;

    float v[16];
    float m = -1e30f;
#pragma unroll
    for (int i = 0; i < 16; i++) {
        v[i] = p[t + 256 * i];
        m = fmaxf(m, v[i]);
    }

    __shared__ float redmax[8];
    __shared__ float redsum[8];
#pragma unroll
    for (int o = 16; o > 0; o >>= 1)
        m = fmaxf(m, __shfl_xor_sync(0xffffffffu, m, o));
    if ((t & 31) == 0) redmax[t >> 5] = m;
    __syncthreads();
    m = redmax[0];
#pragma unroll
    for (int w = 1; w < 8; w++) m = fmaxf(m, redmax[w]);

    float sum = 0.0f;
#pragma unroll
    for (int i = 0; i < 16; i++) {
        v[i] = __expf(v[i] - m);
        sum += v[i];
    }
#pragma unroll
    for (int o = 16; o > 0; o >>= 1)
        sum += __shfl_xor_sync(0xffffffffu, sum, o);
    if ((t & 31) == 0) redsum[t >> 5] = sum;
    __syncthreads();
    sum = 0.0f;
#pragma unroll
    for (int w = 0; w < 8; w++) sum += redsum[w];

    const float inv = 1.0f / sum;
#pragma unroll
    for (int i = 0; i < 16; i++) p[t + 256 * i] = v[i] * inv;
}

// ---------------------------------------------------------------------------
// Launch: 3 projection GEMMs -> scores GEMM -> softmax -> A*V GEMM.
// All on the capture stream; sequential launches give the needed ordering.
// ---------------------------------------------------------------------------
extern "C" void kernel_launch(void* const* d_in, const int* in_sizes, int n_in,
                              void* d_out, int out_size)
{
    const float* X  = (const float*)d_in[0];
    const float* Wq = (const float*)d_in[1];
    const float* bq = (const float*)d_in[2];
    const float* Wk = (const float*)d_in[3];
    const float* bk = (const float*)d_in[4];
    const float* Wv = (const float*)d_in[5];
    const float* bv = (const float*)d_in[6];
    float* out = (float*)d_out;

    float *q, *k, *v, *s;
    cudaGetSymbolAddress((void**)&q, g_q);
    cudaGetSymbolAddress((void**)&k, g_k);
    cudaGetSymbolAddress((void**)&v, g_v);
    cudaGetSymbolAddress((void**)&s, g_s);

    const int M = NBATCH * SEQ;  // 16384 rows for the fused projections
    dim3 blk(256);

    // Projections: C = X * W^T + b   (M x 1024, K = 1024)
    dim3 gp(DIM / BN, M / BM, 1);  // (8, 128)
    sgemm_kernel<true, true><<<gp, blk>>>(X, Wq, bq, q, M, DIM, DIM, 0, 0, 0, 1.0f);
    sgemm_kernel<true, true><<<gp, blk>>>(X, Wk, bk, k, M, DIM, DIM, 0, 0, 0, 1.0f);
    sgemm_kernel<true, true><<<gp, blk>>>(X, Wv, bv, v, M, DIM, DIM, 0, 0, 0, 1.0f);

    // Scores: S = (Q * K^T) / sqrt(1024), per batch
    dim3 gs(SEQ / BN, SEQ / BM, NBATCH);  // (32, 32, 4)
    sgemm_kernel<true, false><<<gs, blk>>>(
        q, k, nullptr, s, SEQ, SEQ, DIM,
        (size_t)SEQ * DIM, (size_t)SEQ * DIM, (size_t)SEQ * SEQ, 1.0f / 32.0f);

    // Row softmax over all NBATCH*SEQ rows
    softmax_kernel<<<NBATCH * SEQ, 256>>>(s);

    // Output: O = Attn * V, per batch
    dim3 ga(DIM / BN, SEQ / BM, NBATCH);  // (8, 32, 4)
    sgemm_kernel<false, false><<<ga, blk>>>(
        s, v, nullptr, out, SEQ, DIM, SEQ,
        (size_t)SEQ * SEQ, (size_t)SEQ * DIM, (size_t)SEQ * DIM, 1.0f);
}

// round 3
// speedup vs baseline: 2.7822x; 2.7822x over previous
#include <cuda_runtime.h>
#include <cuda_bf16.h>
#include <cstdint>
#include <cstddef>

#define NB  4
#define SEQ 4096
#define DIM 1024
#define MTOT (NB * SEQ)

// ---------------------------------------------------------------------------
// Scratch (static device globals; runtime allocation is forbidden)
// ---------------------------------------------------------------------------
__device__ __nv_bfloat16 g_Xh[(size_t)MTOT * DIM];
__device__ __nv_bfloat16 g_Xl[(size_t)MTOT * DIM];
__device__ __nv_bfloat16 g_Wqh[(size_t)DIM * DIM];
__device__ __nv_bfloat16 g_Wql[(size_t)DIM * DIM];
__device__ __nv_bfloat16 g_Wkh[(size_t)DIM * DIM];
__device__ __nv_bfloat16 g_Wkl[(size_t)DIM * DIM];
__device__ __nv_bfloat16 g_Wvh[(size_t)DIM * DIM];
__device__ __nv_bfloat16 g_Wvl[(size_t)DIM * DIM];
__device__ __nv_bfloat16 g_qh[(size_t)MTOT * DIM];
__device__ __nv_bfloat16 g_ql[(size_t)MTOT * DIM];
__device__ __nv_bfloat16 g_kh[(size_t)MTOT * DIM];
__device__ __nv_bfloat16 g_kl[(size_t)MTOT * DIM];
__device__ __nv_bfloat16 g_vh[(size_t)MTOT * DIM];
__device__ __nv_bfloat16 g_vl[(size_t)MTOT * DIM];
__device__ __nv_bfloat16 g_vth[(size_t)MTOT * DIM];
__device__ __nv_bfloat16 g_vtl[(size_t)MTOT * DIM];
__device__ float         g_s [(size_t)NB * SEQ * SEQ];
__device__ __nv_bfloat16 g_ah[(size_t)NB * SEQ * SEQ];
__device__ __nv_bfloat16 g_al[(size_t)NB * SEQ * SEQ];

// ---------------------------------------------------------------------------
// PTX helpers
// ---------------------------------------------------------------------------
__device__ __forceinline__ uint32_t s2u(const void* p) {
    uint32_t a;
    asm("{ .reg .u64 t; cvta.to.shared.u64 t, %1; cvt.u32.u64 %0, t; }"
        : "=r"(a) : "l"(p));
    return a;
}
__device__ __forceinline__ void cpasync16(uint32_t s, const void* g) {
    asm volatile("cp.async.cg.shared.global [%0], [%1], 16;"
                 :: "r"(s), "l"(g) : "memory");
}
__device__ __forceinline__ void cp_commit() {
    asm volatile("cp.async.commit_group;" ::: "memory");
}
__device__ __forceinline__ void ldsm4(uint32_t& r0, uint32_t& r1,
                                      uint32_t& r2, uint32_t& r3, uint32_t a) {
    asm volatile("ldmatrix.sync.aligned.m8n8.x4.shared.b16 {%0,%1,%2,%3}, [%4];"
                 : "=r"(r0), "=r"(r1), "=r"(r2), "=r"(r3) : "r"(a));
}
__device__ __forceinline__ void mma16816(float* c, const uint32_t* a,
                                         const uint32_t* b) {
    asm volatile(
        "mma.sync.aligned.m16n8k16.row.col.f32.bf16.bf16.f32 "
        "{%0,%1,%2,%3}, {%4,%5,%6,%7}, {%8,%9}, {%0,%1,%2,%3};"
        : "+f"(c[0]), "+f"(c[1]), "+f"(c[2]), "+f"(c[3])
        : "r"(a[0]), "r"(a[1]), "r"(a[2]), "r"(a[3]), "r"(b[0]), "r"(b[1]));
}

// ---------------------------------------------------------------------------
// Split-bf16 GEMM:  C[M,N] = (Ah+Al)[M,K] * ((Bh+Bl)[N,K])^T  (3 HMMAs/tile)
// 256 thr, block tile 128x128x32, warp tile 32x64, cp.async double buffer.
// EPI 0: += bias, write bf16 hi/lo pair.  EPI 1: write fp32 * alpha.
// SMEM per stage: 4 arrays (Ah,Al,Bh,Bl), each 128 rows x 80 bytes (32 bf16
// + 8 pad) -> ldmatrix bank-conflict-free. Stage = 40960 B, 2 stages.
// ---------------------------------------------------------------------------
constexpr int BM = 128, BN = 128, BK = 32;
constexpr int PITCHB  = 80;
constexpr int ARR_B   = 128 * PITCHB;   // 10240
constexpr int STAGE_B = 4 * ARR_B;      // 40960
constexpr int SMEM_TOTAL = 2 * STAGE_B; // 81920

template <int EPI>
__global__ void __launch_bounds__(256, 1)
gemm_mma(const __nv_bfloat16* __restrict__ Ahg, const __nv_bfloat16* __restrict__ Alg,
         const __nv_bfloat16* __restrict__ Bhg, const __nv_bfloat16* __restrict__ Blg,
         const float* __restrict__ bias,
         __nv_bfloat16* __restrict__ Ch, __nv_bfloat16* __restrict__ Cl,
         float* __restrict__ Cf,
         int M, int N, int K,
         size_t sA, size_t sB, size_t sC, float alpha)
{
    extern __shared__ char smem[];
    const int tid  = threadIdx.x;
    const int lane = tid & 31, warp = tid >> 5;
    const int wm = warp >> 1, wn = warp & 1;
    const int m0 = blockIdx.y * BM, n0 = blockIdx.x * BN;
    const size_t zb = blockIdx.z;

    const __nv_bfloat16* Ah = Ahg + zb * sA;
    const __nv_bfloat16* Al = Alg + zb * sA;
    const __nv_bfloat16* Bh = Bhg + zb * sB;
    const __nv_bfloat16* Bl = Blg + zb * sB;

    const uint32_t sbase = s2u(smem);

    // ---- per-thread cp.async slots: 8 x 16B per slab ----
    const __nv_bfloat16* gsrc[8];
    uint32_t soff[8];
#pragma unroll
    for (int j = 0; j < 8; j++) {
        int a   = j >> 1;                    // 0:Ah 1:Al 2:Bh 3:Bl
        int cia = ((j & 1) << 8) | tid;      // 0..511
        int row = cia >> 2, c16 = cia & 3;
        const __nv_bfloat16* bp = (a == 0) ? Ah : (a == 1) ? Al : (a == 2) ? Bh : Bl;
        int r0 = (a < 2) ? m0 : n0;
        gsrc[j] = bp + (size_t)(r0 + row) * K + c16 * 8;
        soff[j] = a * ARR_B + row * PITCHB + c16 * 16;
    }

    const int NS = K / BK;

    auto issue = [&](int slab) {
        uint32_t st = sbase + (slab & 1) * STAGE_B;
#pragma unroll
        for (int j = 0; j < 8; j++)
            cpasync16(st + soff[j], gsrc[j] + slab * BK);
    };

    issue(0); cp_commit();
    if (NS > 1) issue(1);
    cp_commit();

    float acc[2][8][4];
#pragma unroll
    for (int t = 0; t < 2; t++)
#pragma unroll
        for (int nt = 0; nt < 8; nt++)
#pragma unroll
            for (int f = 0; f < 4; f++) acc[t][nt][f] = 0.0f;

    // ldmatrix relative offsets
    const uint32_t aoff = (uint32_t)((wm * 32 + (lane & 15)) * PITCHB +
                                     (((lane >> 4) << 3) << 1));
    const uint32_t boff = (uint32_t)((wn * 64 + ((lane >> 4) << 3) + (lane & 7)) * PITCHB +
                                     (((lane >> 3) & 1) << 4));

    for (int s = 0; s < NS; s++) {
        asm volatile("cp.async.wait_group 1;" ::: "memory");
        __syncthreads();
        const uint32_t st = sbase + (s & 1) * STAGE_B;
#pragma unroll
        for (int kk = 0; kk < 2; kk++) {
            const uint32_t kb = kk * 32;     // 16 bf16 = 32 bytes
            uint32_t bh[16], bl[16];
#pragma unroll
            for (int p = 0; p < 4; p++) {
                ldsm4(bh[4*p], bh[4*p+1], bh[4*p+2], bh[4*p+3],
                      st + 2 * ARR_B + boff + p * 16 * PITCHB + kb);
                ldsm4(bl[4*p], bl[4*p+1], bl[4*p+2], bl[4*p+3],
                      st + 3 * ARR_B + boff + p * 16 * PITCHB + kb);
            }
#pragma unroll
            for (int t = 0; t < 2; t++) {
                uint32_t ah[4], al[4];
                ldsm4(ah[0], ah[1], ah[2], ah[3],
                      st + 0 * ARR_B + aoff + t * 16 * PITCHB + kb);
                ldsm4(al[0], al[1], al[2], al[3],
                      st + 1 * ARR_B + aoff + t * 16 * PITCHB + kb);
#pragma unroll
                for (int nt = 0; nt < 8; nt++) {
                    mma16816(acc[t][nt], ah, &bh[2 * nt]);
                    mma16816(acc[t][nt], al, &bh[2 * nt]);
                    mma16816(acc[t][nt], ah, &bl[2 * nt]);
                }
            }
        }
        __syncthreads();
        if (s + 2 < NS) issue(s + 2);
        cp_commit();
    }
    asm volatile("cp.async.wait_group 0;" ::: "memory");

    // ---- epilogue ----
    const int mrow = lane >> 2;
    const int ncol = (lane & 3) * 2;
#pragma unroll
    for (int t = 0; t < 2; t++)
#pragma unroll
        for (int nt = 0; nt < 8; nt++)
#pragma unroll
            for (int hp = 0; hp < 2; hp++) {
                int m = m0 + wm * 32 + t * 16 + mrow + hp * 8;
                int n = n0 + wn * 64 + nt * 8 + ncol;
                float v0 = acc[t][nt][hp * 2 + 0];
                float v1 = acc[t][nt][hp * 2 + 1];
                size_t off = zb * sC + (size_t)m * N + n;
                if (EPI == 0) {
                    v0 += bias[n]; v1 += bias[n + 1];
                    __nv_bfloat16 h0 = __float2bfloat16(v0);
                    __nv_bfloat16 h1 = __float2bfloat16(v1);
                    __nv_bfloat16 l0 = __float2bfloat16(v0 - __bfloat162float(h0));
                    __nv_bfloat16 l1 = __float2bfloat16(v1 - __bfloat162float(h1));
                    *(__nv_bfloat162*)(Ch + off) = __nv_bfloat162{h0, h1};
                    *(__nv_bfloat162*)(Cl + off) = __nv_bfloat162{l0, l1};
                } else {
                    *(float2*)(Cf + off) = make_float2(v0 * alpha, v1 * alpha);
                }
            }
}

// ---------------------------------------------------------------------------
// fp32 -> (hi, lo) bf16 split, float4-vectorized
// ---------------------------------------------------------------------------
__global__ void split_kernel(const float* __restrict__ x,
                             __nv_bfloat16* __restrict__ h,
                             __nv_bfloat16* __restrict__ l, size_t n4)
{
    size_t i  = (size_t)blockIdx.x * blockDim.x + threadIdx.x;
    size_t st = (size_t)gridDim.x * blockDim.x;
    for (; i < n4; i += st) {
        float4 v = ((const float4*)x)[i];
        __nv_bfloat16 h0 = __float2bfloat16(v.x), h1 = __float2bfloat16(v.y);
        __nv_bfloat16 h2 = __float2bfloat16(v.z), h3 = __float2bfloat16(v.w);
        __nv_bfloat16 l0 = __float2bfloat16(v.x - __bfloat162float(h0));
        __nv_bfloat16 l1 = __float2bfloat16(v.y - __bfloat162float(h1));
        __nv_bfloat16 l2 = __float2bfloat16(v.z - __bfloat162float(h2));
        __nv_bfloat16 l3 = __float2bfloat16(v.w - __bfloat162float(h3));
        ((__nv_bfloat162*)h)[2 * i]     = __nv_bfloat162{h0, h1};
        ((__nv_bfloat162*)h)[2 * i + 1] = __nv_bfloat162{h2, h3};
        ((__nv_bfloat162*)l)[2 * i]     = __nv_bfloat162{l0, l1};
        ((__nv_bfloat162*)l)[2 * i + 1] = __nv_bfloat162{l2, l3};
    }
}

// ---------------------------------------------------------------------------
// 32x32 tiled bf16 transpose: [b][SEQ][DIM] -> [b][DIM][SEQ]
// ---------------------------------------------------------------------------
__global__ void transpose_kernel(const __nv_bfloat16* __restrict__ in,
                                 __nv_bfloat16* __restrict__ out)
{
    __shared__ __nv_bfloat16 t[32][34];
    const size_t b = blockIdx.z;
    const __nv_bfloat16* src = in  + b * (size_t)SEQ * DIM;
    __nv_bfloat16*       dst = out + b * (size_t)SEQ * DIM;
    const int s0 = blockIdx.y * 32, d0 = blockIdx.x * 32;
    const int tx = threadIdx.x & 31, ty = threadIdx.x >> 5;
#pragma unroll
    for (int i = 0; i < 4; i++)
        t[ty + i * 8][tx] = src[(size_t)(s0 + ty + i * 8) * DIM + d0 + tx];
    __syncthreads();
#pragma unroll
    for (int i = 0; i < 4; i++)
        dst[(size_t)(d0 + ty + i * 8) * SEQ + s0 + tx] = t[tx][ty + i * 8];
}

// ---------------------------------------------------------------------------
// Row softmax over 4096-wide fp32 rows -> bf16 hi/lo attention weights
// ---------------------------------------------------------------------------
__global__ void __launch_bounds__(256)
softmax_split_kernel(const float* __restrict__ S,
                     __nv_bfloat16* __restrict__ Ah,
                     __nv_bfloat16* __restrict__ Al)
{
    const float* p = S + (size_t)blockIdx.x * SEQ;
    __nv_bfloat16* ph = Ah + (size_t)blockIdx.x * SEQ;
    __nv_bfloat16* pl = Al + (size_t)blockIdx.x * SEQ;
    const int t = threadIdx.x;

    float v[16];
    float m = -1e30f;
#pragma unroll
    for (int i = 0; i < 16; i++) {
        v[i] = p[t + 256 * i];
        m = fmaxf(m, v[i]);
    }
    __shared__ float redmax[8], redsum[8];
#pragma unroll
    for (int o = 16; o > 0; o >>= 1)
        m = fmaxf(m, __shfl_xor_sync(0xffffffffu, m, o));
    if ((t & 31) == 0) redmax[t >> 5] = m;
    __syncthreads();
    m = redmax[0];
#pragma unroll
    for (int w = 1; w < 8; w++) m = fmaxf(m, redmax[w]);

    float sum = 0.0f;
#pragma unroll
    for (int i = 0; i < 16; i++) {
        v[i] = __expf(v[i] - m);
        sum += v[i];
    }
#pragma unroll
    for (int o = 16; o > 0; o >>= 1)
        sum += __shfl_xor_sync(0xffffffffu, sum, o);
    if ((t & 31) == 0) redsum[t >> 5] = sum;
    __syncthreads();
    sum = 0.0f;
#pragma unroll
    for (int w = 0; w < 8; w++) sum += redsum[w];

    const float inv = 1.0f / sum;
#pragma unroll
    for (int i = 0; i < 16; i++) {
        float pv = v[i] * inv;
        __nv_bfloat16 h = __float2bfloat16(pv);
        __nv_bfloat16 l = __float2bfloat16(pv - __bfloat162float(h));
        ph[t + 256 * i] = h;
        pl[t + 256 * i] = l;
    }
}

// ---------------------------------------------------------------------------
extern "C" void kernel_launch(void* const* d_in, const int* in_sizes, int n_in,
                              void* d_out, int out_size)
{
    const float* X  = (const float*)d_in[0];
    const float* Wq = (const float*)d_in[1];
    const float* bq = (const float*)d_in[2];
    const float* Wk = (const float*)d_in[3];
    const float* bk = (const float*)d_in[4];
    const float* Wv = (const float*)d_in[5];
    const float* bv = (const float*)d_in[6];
    float* out = (float*)d_out;

    __nv_bfloat16 *Xh, *Xl, *Wqh, *Wql, *Wkh, *Wkl, *Wvh, *Wvl;
    __nv_bfloat16 *qh, *ql, *kh, *kl, *vh, *vl, *vth, *vtl, *ah, *al;
    float* s;
    cudaGetSymbolAddress((void**)&Xh,  g_Xh);  cudaGetSymbolAddress((void**)&Xl,  g_Xl);
    cudaGetSymbolAddress((void**)&Wqh, g_Wqh); cudaGetSymbolAddress((void**)&Wql, g_Wql);
    cudaGetSymbolAddress((void**)&Wkh, g_Wkh); cudaGetSymbolAddress((void**)&Wkl, g_Wkl);
    cudaGetSymbolAddress((void**)&Wvh, g_Wvh); cudaGetSymbolAddress((void**)&Wvl, g_Wvl);
    cudaGetSymbolAddress((void**)&qh,  g_qh);  cudaGetSymbolAddress((void**)&ql,  g_ql);
    cudaGetSymbolAddress((void**)&kh,  g_kh);  cudaGetSymbolAddress((void**)&kl,  g_kl);
    cudaGetSymbolAddress((void**)&vh,  g_vh);  cudaGetSymbolAddress((void**)&vl,  g_vl);
    cudaGetSymbolAddress((void**)&vth, g_vth); cudaGetSymbolAddress((void**)&vtl, g_vtl);
    cudaGetSymbolAddress((void**)&ah,  g_ah);  cudaGetSymbolAddress((void**)&al,  g_al);
    cudaGetSymbolAddress((void**)&s,   g_s);

    cudaFuncSetAttribute(gemm_mma<0>, cudaFuncAttributeMaxDynamicSharedMemorySize, SMEM_TOTAL);
    cudaFuncSetAttribute(gemm_mma<1>, cudaFuncAttributeMaxDynamicSharedMemorySize, SMEM_TOTAL);

    // 1) hi/lo splits of inputs
    split_kernel<<<2048, 256>>>(X,  Xh,  Xl,  (size_t)MTOT * DIM / 4);
    split_kernel<<<512,  256>>>(Wq, Wqh, Wql, (size_t)DIM * DIM / 4);
    split_kernel<<<512,  256>>>(Wk, Wkh, Wkl, (size_t)DIM * DIM / 4);
    split_kernel<<<512,  256>>>(Wv, Wvh, Wvl, (size_t)DIM * DIM / 4);

    // 2) projections: q/k/v = X*W^T + b  (M=16384, N=K=1024)
    dim3 gp(DIM / BN, MTOT / BM, 1);
    gemm_mma<0><<<gp, 256, SMEM_TOTAL>>>(Xh, Xl, Wqh, Wql, bq, qh, ql, nullptr,
                                         MTOT, DIM, DIM, 0, 0, 0, 1.0f);
    gemm_mma<0><<<gp, 256, SMEM_TOTAL>>>(Xh, Xl, Wkh, Wkl, bk, kh, kl, nullptr,
                                         MTOT, DIM, DIM, 0, 0, 0, 1.0f);
    gemm_mma<0><<<gp, 256, SMEM_TOTAL>>>(Xh, Xl, Wvh, Wvl, bv, vh, vl, nullptr,
                                         MTOT, DIM, DIM, 0, 0, 0, 1.0f);

    // 3) V^T for the A*V GEMM (B operand must be K-major)
    dim3 gt(DIM / 32, SEQ / 32, NB);
    transpose_kernel<<<gt, 256>>>(vh, vth);
    transpose_kernel<<<gt, 256>>>(vl, vtl);

    // 4) scores = (Q K^T) / 32, per batch
    dim3 gs(SEQ / BN, SEQ / BM, NB);
    gemm_mma<1><<<gs, 256, SMEM_TOTAL>>>(qh, ql, kh, kl, nullptr, nullptr, nullptr, s,
                                         SEQ, SEQ, DIM,
                                         (size_t)SEQ * DIM, (size_t)SEQ * DIM,
                                         (size_t)SEQ * SEQ, 1.0f / 32.0f);

    // 5) softmax -> bf16 hi/lo attention weights
    softmax_split_kernel<<<MTOT, 256>>>(s, ah, al);

    // 6) out = A * V   (A [4096,4096] K-major, B = V^T [1024,4096] K-major)
    dim3 go(DIM / BN, SEQ / BM, NB);
    gemm_mma<1><<<go, 256, SMEM_TOTAL>>>(ah, al, vth, vtl, nullptr, nullptr, nullptr, out,
                                         SEQ, DIM, SEQ,
                                         (size_t)SEQ * SEQ, (size_t)SEQ * DIM,
                                         (size_t)SEQ * DIM, 1.0f);
}

// round 5
// speedup vs baseline: 4.0310x; 1.4488x over previous
#include <cuda_runtime.h>
#include <cuda_fp16.h>
#include <cstdint>
#include <cstddef>

#define NB  4
#define SEQ 4096
#define DIM 1024
#define MTOT (NB * SEQ)

// ---------------------------------------------------------------------------
// Scratch (static device globals; runtime allocation is forbidden)
// ---------------------------------------------------------------------------
__device__ __half g_Xh[(size_t)MTOT * DIM];
__device__ __half g_Xl[(size_t)MTOT * DIM];
__device__ __half g_Wq[(size_t)DIM * DIM];
__device__ __half g_Wk[(size_t)DIM * DIM];
__device__ __half g_Wv[(size_t)DIM * DIM];
__device__ __half g_Qh[(size_t)MTOT * DIM];
__device__ __half g_Ql[(size_t)MTOT * DIM];
__device__ __half g_K [(size_t)MTOT * DIM];
__device__ __half g_V [(size_t)MTOT * DIM];
__device__ __half g_VT[(size_t)MTOT * DIM];
__device__ float  g_S [(size_t)NB * SEQ * SEQ];
__device__ __half g_Ah[(size_t)NB * SEQ * SEQ];
__device__ __half g_Al[(size_t)NB * SEQ * SEQ];

// ---------------------------------------------------------------------------
// PTX helpers
// ---------------------------------------------------------------------------
__device__ __forceinline__ uint32_t s2u(const void* p) {
    uint32_t a;
    asm("{ .reg .u64 t; cvta.to.shared.u64 t, %1; cvt.u32.u64 %0, t; }"
        : "=r"(a) : "l"(p));
    return a;
}
__device__ __forceinline__ void cpasync16(uint32_t s, const void* g) {
    asm volatile("cp.async.cg.shared.global [%0], [%1], 16;"
                 :: "r"(s), "l"(g) : "memory");
}
__device__ __forceinline__ void cp_commit() {
    asm volatile("cp.async.commit_group;" ::: "memory");
}
__device__ __forceinline__ void ldsm4(uint32_t& r0, uint32_t& r1,
                                      uint32_t& r2, uint32_t& r3, uint32_t a) {
    asm volatile("ldmatrix.sync.aligned.m8n8.x4.shared.b16 {%0,%1,%2,%3}, [%4];"
                 : "=r"(r0), "=r"(r1), "=r"(r2), "=r"(r3) : "r"(a));
}
__device__ __forceinline__ void mma16816(float* c, const uint32_t* a,
                                         const uint32_t* b) {
    asm volatile(
        "mma.sync.aligned.m16n8k16.row.col.f32.f16.f16.f32 "
        "{%0,%1,%2,%3}, {%4,%5,%6,%7}, {%8,%9}, {%0,%1,%2,%3};"
        : "+f"(c[0]), "+f"(c[1]), "+f"(c[2]), "+f"(c[3])
        : "r"(a[0]), "r"(a[1]), "r"(a[2]), "r"(a[3]), "r"(b[0]), "r"(b[1]));
}
__device__ __forceinline__ void splith(float v, __half& h, __half& l) {
    h = __float2half(v);
    l = __float2half(v - __half2float(h));
}
__device__ __forceinline__ uint32_t pr2h(__half a, __half b) {
    return ((uint32_t)__half_as_ushort(b) << 16) | __half_as_ushort(a);
}

// ---------------------------------------------------------------------------
// Split-fp16 GEMM:  C[M,N] = (Ah+Al)[M,K] * (B[N,K])^T   (2 HMMAs per tile)
// 256 thr, block tile 128x128x32, warp tile 32x64, cp.async 3-stage pipeline,
// 2 CTAs/SM.
// EPI 0: +bias, write fp16 hi/lo pair.  EPI 1: +bias, write fp16 single.
// EPI 2: write fp32 * alpha.
// SMEM/stage: 3 arrays (Ah, Al, B), each 128 rows x 80 B (64 data + 16 pad)
// -> ldmatrix conflict-free. Stage = 30720 B, 3 stages = 92160 B.
// ---------------------------------------------------------------------------
constexpr int BM = 128, BN = 128, BK = 32;
constexpr int PITCHB  = 80;
constexpr int ARR_B   = 128 * PITCHB;   // 10240
constexpr int STAGE_B = 3 * ARR_B;      // 30720
constexpr int NSTAGE  = 3;
constexpr int SMEM_TOTAL = NSTAGE * STAGE_B;  // 92160

template <int EPI>
__global__ void __launch_bounds__(256, 2)
gemm_mma(const __half* __restrict__ Ahg, const __half* __restrict__ Alg,
         const __half* __restrict__ Bg,
         const float* __restrict__ bias,
         __half* __restrict__ Ch, __half* __restrict__ Cl,
         float* __restrict__ Cf,
         int M, int N, int K,
         size_t sA, size_t sB, size_t sC, float alpha)
{
    extern __shared__ char smem[];
    const int tid  = threadIdx.x;
    const int lane = tid & 31, warp = tid >> 5;
    const int wm = warp >> 1, wn = warp & 1;
    const int m0 = blockIdx.y * BM, n0 = blockIdx.x * BN;
    const size_t zb = blockIdx.z;

    const __half* Ah = Ahg + zb * sA;
    const __half* Al = Alg + zb * sA;
    const __half* B  = Bg  + zb * sB;

    const uint32_t sbase = s2u(smem);

    // ---- per-thread cp.async slots: 6 x 16B per slab ----
    const __half* gsrc[6];
    uint32_t soff[6];
#pragma unroll
    for (int j = 0; j < 6; j++) {
        int a   = j >> 1;                    // 0:Ah 1:Al 2:B
        int cia = ((j & 1) << 8) | tid;      // 0..511
        int row = cia >> 2, c16 = cia & 3;
        const __half* bp = (a == 0) ? Ah : (a == 1) ? Al : B;
        int r0 = (a < 2) ? m0 : n0;
        gsrc[j] = bp + (size_t)(r0 + row) * K + c16 * 8;
        soff[j] = a * ARR_B + row * PITCHB + c16 * 16;
    }

    const int NS = K / BK;

    auto issue = [&](int slab) {
        uint32_t st = sbase + (slab % NSTAGE) * STAGE_B;
#pragma unroll
        for (int j = 0; j < 6; j++)
            cpasync16(st + soff[j], gsrc[j] + slab * BK);
    };

    issue(0); cp_commit();
    issue(1); cp_commit();

    float acc[2][8][4];
#pragma unroll
    for (int t = 0; t < 2; t++)
#pragma unroll
        for (int nt = 0; nt < 8; nt++)
#pragma unroll
            for (int f = 0; f < 4; f++) acc[t][nt][f] = 0.0f;

    // ldmatrix relative offsets (identical layout to the verified r3 kernel)
    const uint32_t aoff = (uint32_t)((wm * 32 + (lane & 15)) * PITCHB +
                                     (((lane >> 4) << 3) << 1));
    const uint32_t boff = (uint32_t)((wn * 64 + ((lane >> 4) << 3) + (lane & 7)) * PITCHB +
                                     (((lane >> 3) & 1) << 4));

    for (int s = 0; s < NS; s++) {
        asm volatile("cp.async.wait_group 1;" ::: "memory");
        __syncthreads();
        // issue the slab after next into its (now free) buffer
        if (s + 2 < NS) issue(s + 2);
        cp_commit();

        const uint32_t st = sbase + (s % NSTAGE) * STAGE_B;
#pragma unroll
        for (int kk = 0; kk < 2; kk++) {
            const uint32_t kb = kk * 32;     // 16 halves = 32 bytes
            uint32_t bh[16];
#pragma unroll
            for (int p = 0; p < 4; p++)
                ldsm4(bh[4*p], bh[4*p+1], bh[4*p+2], bh[4*p+3],
                      st + 2 * ARR_B + boff + p * 16 * PITCHB + kb);
#pragma unroll
            for (int t = 0; t < 2; t++) {
                uint32_t ah[4], al[4];
                ldsm4(ah[0], ah[1], ah[2], ah[3],
                      st + 0 * ARR_B + aoff + t * 16 * PITCHB + kb);
                ldsm4(al[0], al[1], al[2], al[3],
                      st + 1 * ARR_B + aoff + t * 16 * PITCHB + kb);
#pragma unroll
                for (int nt = 0; nt < 8; nt++) {
                    mma16816(acc[t][nt], ah, &bh[2 * nt]);
                    mma16816(acc[t][nt], al, &bh[2 * nt]);
                }
            }
        }
        __syncthreads();
    }
    asm volatile("cp.async.wait_group 0;" ::: "memory");

    // ---- epilogue ----
    const int mrow = lane >> 2;
    const int ncol = (lane & 3) * 2;
#pragma unroll
    for (int t = 0; t < 2; t++)
#pragma unroll
        for (int nt = 0; nt < 8; nt++)
#pragma unroll
            for (int hp = 0; hp < 2; hp++) {
                int m = m0 + wm * 32 + t * 16 + mrow + hp * 8;
                int n = n0 + wn * 64 + nt * 8 + ncol;
                float v0 = acc[t][nt][hp * 2 + 0];
                float v1 = acc[t][nt][hp * 2 + 1];
                size_t off = zb * sC + (size_t)m * N + n;
                if (EPI == 0) {
                    v0 += bias[n]; v1 += bias[n + 1];
                    __half h0, l0, h1, l1;
                    splith(v0, h0, l0); splith(v1, h1, l1);
                    *(uint32_t*)(Ch + off) = pr2h(h0, h1);
                    *(uint32_t*)(Cl + off) = pr2h(l0, l1);
                } else if (EPI == 1) {
                    v0 += bias[n]; v1 += bias[n + 1];
                    *(uint32_t*)(Ch + off) = pr2h(__float2half(v0), __float2half(v1));
                } else {
                    *(float2*)(Cf + off) = make_float2(v0 * alpha, v1 * alpha);
                }
            }
}

// ---------------------------------------------------------------------------
// fp32 -> (hi, lo) fp16 split, float4-vectorized
// ---------------------------------------------------------------------------
__global__ void split_kernel(const float* __restrict__ x,
                             __half* __restrict__ h, __half* __restrict__ l,
                             size_t n4)
{
    size_t i  = (size_t)blockIdx.x * blockDim.x + threadIdx.x;
    size_t st = (size_t)gridDim.x * blockDim.x;
    for (; i < n4; i += st) {
        float4 v = ((const float4*)x)[i];
        __half h0, l0, h1, l1, h2, l2, h3, l3;
        splith(v.x, h0, l0); splith(v.y, h1, l1);
        splith(v.z, h2, l2); splith(v.w, h3, l3);
        ((uint2*)h)[i] = make_uint2(pr2h(h0, h1), pr2h(h2, h3));
        ((uint2*)l)[i] = make_uint2(pr2h(l0, l1), pr2h(l2, l3));
    }
}

// fp32 -> fp16 convert (B operands need no lo part)
__global__ void conv_kernel(const float* __restrict__ x,
                            __half* __restrict__ h, size_t n4)
{
    size_t i  = (size_t)blockIdx.x * blockDim.x + threadIdx.x;
    size_t st = (size_t)gridDim.x * blockDim.x;
    for (; i < n4; i += st) {
        float4 v = ((const float4*)x)[i];
        ((uint2*)h)[i] = make_uint2(
            pr2h(__float2half(v.x), __float2half(v.y)),
            pr2h(__float2half(v.z), __float2half(v.w)));
    }
}

// ---------------------------------------------------------------------------
// 32x32 tiled fp16 transpose: [b][SEQ][DIM] -> [b][DIM][SEQ]
// ---------------------------------------------------------------------------
__global__ void transpose_kernel(const __half* __restrict__ in,
                                 __half* __restrict__ out)
{
    __shared__ __half t[32][34];
    const size_t b = blockIdx.z;
    const __half* src = in  + b * (size_t)SEQ * DIM;
    __half*       dst = out + b * (size_t)SEQ * DIM;
    const int s0 = blockIdx.y * 32, d0 = blockIdx.x * 32;
    const int tx = threadIdx.x & 31, ty = threadIdx.x >> 5;
#pragma unroll
    for (int i = 0; i < 4; i++)
        t[ty + i * 8][tx] = src[(size_t)(s0 + ty + i * 8) * DIM + d0 + tx];
    __syncthreads();
#pragma unroll
    for (int i = 0; i < 4; i++)
        dst[(size_t)(d0 + ty + i * 8) * SEQ + s0 + tx] = t[tx][ty + i * 8];
}

// ---------------------------------------------------------------------------
// Row softmax over 4096-wide fp32 rows -> fp16 hi/lo attention weights
// ---------------------------------------------------------------------------
__global__ void __launch_bounds__(256)
softmax_split_kernel(const float* __restrict__ S,
                     __half* __restrict__ Ahp, __half* __restrict__ Alp)
{
    const float* p = S + (size_t)blockIdx.x * SEQ;
    __half* ph = Ahp + (size_t)blockIdx.x * SEQ;
    __half* pl = Alp + (size_t)blockIdx.x * SEQ;
    const int t = threadIdx.x;

    float v[16];
    float m = -1e30f;
#pragma unroll
    for (int i = 0; i < 16; i++) {
        v[i] = p[t + 256 * i];
        m = fmaxf(m, v[i]);
    }
    __shared__ float redmax[8], redsum[8];
#pragma unroll
    for (int o = 16; o > 0; o >>= 1)
        m = fmaxf(m, __shfl_xor_sync(0xffffffffu, m, o));
    if ((t & 31) == 0) redmax[t >> 5] = m;
    __syncthreads();
    m = redmax[0];
#pragma unroll
    for (int w = 1; w < 8; w++) m = fmaxf(m, redmax[w]);

    float sum = 0.0f;
#pragma unroll
    for (int i = 0; i < 16; i++) {
        v[i] = __expf(v[i] - m);
        sum += v[i];
    }
#pragma unroll
    for (int o = 16; o > 0; o >>= 1)
        sum += __shfl_xor_sync(0xffffffffu, sum, o);
    if ((t & 31) == 0) redsum[t >> 5] = sum;
    __syncthreads();
    sum = 0.0f;
#pragma unroll
    for (int w = 0; w < 8; w++) sum += redsum[w];

    const float inv = 1.0f / sum;
#pragma unroll
    for (int i = 0; i < 16; i++) {
        float pv = v[i] * inv;
        __half h, l;
        splith(pv, h, l);
        ph[t + 256 * i] = h;
        pl[t + 256 * i] = l;
    }
}

// ---------------------------------------------------------------------------
extern "C" void kernel_launch(void* const* d_in, const int* in_sizes, int n_in,
                              void* d_out, int out_size)
{
    const float* X  = (const float*)d_in[0];
    const float* Wq = (const float*)d_in[1];
    const float* bq = (const float*)d_in[2];
    const float* Wk = (const float*)d_in[3];
    const float* bk = (const float*)d_in[4];
    const float* Wv = (const float*)d_in[5];
    const float* bv = (const float*)d_in[6];
    float* out = (float*)d_out;

    __half *Xh, *Xl, *Wqp, *Wkp, *Wvp, *Qh, *Ql, *K, *V, *VT, *Ah, *Al;
    float* S;
    cudaGetSymbolAddress((void**)&Xh,  g_Xh);  cudaGetSymbolAddress((void**)&Xl, g_Xl);
    cudaGetSymbolAddress((void**)&Wqp, g_Wq);  cudaGetSymbolAddress((void**)&Wkp, g_Wk);
    cudaGetSymbolAddress((void**)&Wvp, g_Wv);
    cudaGetSymbolAddress((void**)&Qh,  g_Qh);  cudaGetSymbolAddress((void**)&Ql, g_Ql);
    cudaGetSymbolAddress((void**)&K,   g_K);   cudaGetSymbolAddress((void**)&V,  g_V);
    cudaGetSymbolAddress((void**)&VT,  g_VT);
    cudaGetSymbolAddress((void**)&Ah,  g_Ah);  cudaGetSymbolAddress((void**)&Al, g_Al);
    cudaGetSymbolAddress((void**)&S,   g_S);

    cudaFuncSetAttribute(gemm_mma<0>, cudaFuncAttributeMaxDynamicSharedMemorySize, SMEM_TOTAL);
    cudaFuncSetAttribute(gemm_mma<1>, cudaFuncAttributeMaxDynamicSharedMemorySize, SMEM_TOTAL);
    cudaFuncSetAttribute(gemm_mma<2>, cudaFuncAttributeMaxDynamicSharedMemorySize, SMEM_TOTAL);

    // 1) operand prep: X -> hi/lo, W -> fp16
    split_kernel<<<2048, 256>>>(X, Xh, Xl, (size_t)MTOT * DIM / 4);
    conv_kernel<<<512, 256>>>(Wq, Wqp, (size_t)DIM * DIM / 4);
    conv_kernel<<<512, 256>>>(Wk, Wkp, (size_t)DIM * DIM / 4);
    conv_kernel<<<512, 256>>>(Wv, Wvp, (size_t)DIM * DIM / 4);

    // 2) projections: q (hi/lo), k (single), v (single) = X*W^T + b
    dim3 gp(DIM / BN, MTOT / BM, 1);
    gemm_mma<0><<<gp, 256, SMEM_TOTAL>>>(Xh, Xl, Wqp, bq, Qh, Ql, nullptr,
                                         MTOT, DIM, DIM, 0, 0, 0, 1.0f);
    gemm_mma<1><<<gp, 256, SMEM_TOTAL>>>(Xh, Xl, Wkp, bk, K, nullptr, nullptr,
                                         MTOT, DIM, DIM, 0, 0, 0, 1.0f);
    gemm_mma<1><<<gp, 256, SMEM_TOTAL>>>(Xh, Xl, Wvp, bv, V, nullptr, nullptr,
                                         MTOT, DIM, DIM, 0, 0, 0, 1.0f);

    // 3) V^T for the A*V GEMM (B operand must be K-major)
    dim3 gt(DIM / 32, SEQ / 32, NB);
    transpose_kernel<<<gt, 256>>>(V, VT);

    // 4) scores = (Q K^T) / 32, per batch
    dim3 gs(SEQ / BN, SEQ / BM, NB);
    gemm_mma<2><<<gs, 256, SMEM_TOTAL>>>(Qh, Ql, K, nullptr, nullptr, nullptr, S,
                                         SEQ, SEQ, DIM,
                                         (size_t)SEQ * DIM, (size_t)SEQ * DIM,
                                         (size_t)SEQ * SEQ, 1.0f / 32.0f);

    // 5) softmax -> fp16 hi/lo attention weights
    softmax_split_kernel<<<MTOT, 256>>>(S, Ah, Al);

    // 6) out = A * V   (A [4096,4096] K-major, B = V^T [1024,4096] K-major)
    dim3 go(DIM / BN, SEQ / BM, NB);
    gemm_mma<2><<<go, 256, SMEM_TOTAL>>>(Ah, Al, VT, nullptr, nullptr, nullptr, out,
                                         SEQ, DIM, SEQ,
                                         (size_t)SEQ * SEQ, (size_t)SEQ * DIM,
                                         (size_t)SEQ * DIM, 1.0f);
}

// round 7
// speedup vs baseline: 5.9815x; 1.4839x over previous
#include <cuda_runtime.h>
#include <cuda_fp16.h>
#include <cstdint>
#include <cstddef>

#define NB  4
#define SEQ 4096
#define DIM 1024
#define MTOT (NB * SEQ)

// ---------------------------------------------------------------------------
// Scratch (static device globals; runtime allocation is forbidden)
// ---------------------------------------------------------------------------
__device__ __half g_Xh[(size_t)MTOT * DIM];
__device__ __half g_Xl[(size_t)MTOT * DIM];
__device__ __half g_Wq[(size_t)DIM * DIM];
__device__ __half g_Wk[(size_t)DIM * DIM];
__device__ __half g_Wv[(size_t)DIM * DIM];
__device__ __half g_Q [(size_t)MTOT * DIM];
__device__ __half g_K [(size_t)MTOT * DIM];
__device__ __half g_V [(size_t)MTOT * DIM];
__device__ __half g_VT[(size_t)MTOT * DIM];
__device__ __half g_S [(size_t)NB * SEQ * SEQ];
__device__ __half g_A [(size_t)NB * SEQ * SEQ];

// ---------------------------------------------------------------------------
// PTX helpers
// ---------------------------------------------------------------------------
__device__ __forceinline__ uint32_t s2u(const void* p) {
    uint32_t a;
    asm("{ .reg .u64 t; cvta.to.shared.u64 t, %1; cvt.u32.u64 %0, t; }"
        : "=r"(a) : "l"(p));
    return a;
}
__device__ __forceinline__ void cpasync16(uint32_t s, const void* g) {
    asm volatile("cp.async.cg.shared.global [%0], [%1], 16;"
                 :: "r"(s), "l"(g) : "memory");
}
__device__ __forceinline__ void cp_commit() {
    asm volatile("cp.async.commit_group;" ::: "memory");
}
__device__ __forceinline__ void ldsm4(uint32_t& r0, uint32_t& r1,
                                      uint32_t& r2, uint32_t& r3, uint32_t a) {
    asm volatile("ldmatrix.sync.aligned.m8n8.x4.shared.b16 {%0,%1,%2,%3}, [%4];"
                 : "=r"(r0), "=r"(r1), "=r"(r2), "=r"(r3) : "r"(a));
}
__device__ __forceinline__ void mma16816(float* c, const uint32_t* a,
                                         const uint32_t* b) {
    asm volatile(
        "mma.sync.aligned.m16n8k16.row.col.f32.f16.f16.f32 "
        "{%0,%1,%2,%3}, {%4,%5,%6,%7}, {%8,%9}, {%0,%1,%2,%3};"
        : "+f"(c[0]), "+f"(c[1]), "+f"(c[2]), "+f"(c[3])
        : "r"(a[0]), "r"(a[1]), "r"(a[2]), "r"(a[3]), "r"(b[0]), "r"(b[1]));
}
__device__ __forceinline__ void splith(float v, __half& h, __half& l) {
    h = __float2half(v);
    l = __float2half(v - __half2float(h));
}
__device__ __forceinline__ uint32_t pr2h(__half a, __half b) {
    return ((uint32_t)__half_as_ushort(b) << 16) | __half_as_ushort(a);
}

// ---------------------------------------------------------------------------
// fp16 GEMM:  C[M,N] = A[M,K] * (B[N,K])^T
// SPLITA=true : A = Ah + Al (2 HMMAs/tile)  -- projections
// SPLITA=false: A single fp16 (1 HMMA/tile) -- scores, A*V
// 256 thr, block tile 128x128x32, warp tile 32x64, cp.async pipeline,
// 2 CTAs/SM. Stage = NARR x (128 rows x 80 B), padded, ldmatrix conflict-free.
// EPI 0: +bias -> fp16.  EPI 1: *alpha -> fp16.  EPI 2: *alpha -> fp32.
// ---------------------------------------------------------------------------
constexpr int BM = 128, BN = 128, BK = 32;
constexpr int PITCHB = 80;
constexpr int ARR_B  = 128 * PITCHB;   // 10240

template <bool SPLITA, int EPI>
__global__ void __launch_bounds__(256, 2)
gemm_mma(const __half* __restrict__ Ahg, const __half* __restrict__ Alg,
         const __half* __restrict__ Bg,
         const float* __restrict__ bias,
         __half* __restrict__ Ch, float* __restrict__ Cf,
         int M, int N, int K,
         size_t sA, size_t sB, size_t sC, float alpha)
{
    constexpr int NARR   = SPLITA ? 3 : 2;
    constexpr int NSTAGE = SPLITA ? 3 : 4;
    constexpr int PRE    = SPLITA ? 2 : 3;       // slabs in flight
    constexpr int STAGE_B = NARR * ARR_B;
    constexpr int NSLOT  = NARR * 2;             // 16B cp.async slots per thread

    extern __shared__ char smem[];
    const int tid  = threadIdx.x;
    const int lane = tid & 31, warp = tid >> 5;
    const int wm = warp >> 1, wn = warp & 1;
    const int m0 = blockIdx.y * BM, n0 = blockIdx.x * BN;
    const size_t zb = blockIdx.z;

    const __half* Ah = Ahg + zb * sA;
    const __half* Al = SPLITA ? (Alg + zb * sA) : nullptr;
    const __half* B  = Bg  + zb * sB;

    const uint32_t sbase = s2u(smem);

    // ---- per-thread cp.async slots ----
    const __half* gsrc[NSLOT];
    uint32_t soff[NSLOT];
#pragma unroll
    for (int j = 0; j < NSLOT; j++) {
        int a   = j >> 1;                    // array index
        int cia = ((j & 1) << 8) | tid;      // 0..511
        int row = cia >> 2, c16 = cia & 3;
        const __half* bp;
        int r0;
        if (SPLITA) { bp = (a == 0) ? Ah : (a == 1) ? Al : B; r0 = (a < 2) ? m0 : n0; }
        else        { bp = (a == 0) ? Ah : B;                 r0 = (a < 1) ? m0 : n0; }
        gsrc[j] = bp + (size_t)(r0 + row) * K + c16 * 8;
        soff[j] = a * ARR_B + row * PITCHB + c16 * 16;
    }

    const int NS = K / BK;

    auto issue = [&](int slab) {
        uint32_t st = sbase + (slab % NSTAGE) * STAGE_B;
#pragma unroll
        for (int j = 0; j < NSLOT; j++)
            cpasync16(st + soff[j], gsrc[j] + slab * BK);
    };

#pragma unroll
    for (int p = 0; p < PRE; p++) { issue(p); cp_commit(); }

    float acc[2][8][4];
#pragma unroll
    for (int t = 0; t < 2; t++)
#pragma unroll
        for (int nt = 0; nt < 8; nt++)
#pragma unroll
            for (int f = 0; f < 4; f++) acc[t][nt][f] = 0.0f;

    const uint32_t aoff = (uint32_t)((wm * 32 + (lane & 15)) * PITCHB +
                                     (((lane >> 4) << 3) << 1));
    const uint32_t boff = (uint32_t)((wn * 64 + ((lane >> 4) << 3) + (lane & 7)) * PITCHB +
                                     (((lane >> 3) & 1) << 4));
    constexpr int BIDX = SPLITA ? 2 : 1;

    for (int s = 0; s < NS; s++) {
        if (SPLITA)
            asm volatile("cp.async.wait_group 1;" ::: "memory");
        else
            asm volatile("cp.async.wait_group 2;" ::: "memory");
        __syncthreads();
        if (s + PRE < NS) issue(s + PRE);
        cp_commit();

        const uint32_t st = sbase + (s % NSTAGE) * STAGE_B;
#pragma unroll
        for (int kk = 0; kk < 2; kk++) {
            const uint32_t kb = kk * 32;     // 16 halves = 32 bytes
            uint32_t bh[16];
#pragma unroll
            for (int p = 0; p < 4; p++)
                ldsm4(bh[4*p], bh[4*p+1], bh[4*p+2], bh[4*p+3],
                      st + BIDX * ARR_B + boff + p * 16 * PITCHB + kb);
#pragma unroll
            for (int t = 0; t < 2; t++) {
                uint32_t ah[4];
                ldsm4(ah[0], ah[1], ah[2], ah[3],
                      st + aoff + t * 16 * PITCHB + kb);
                if (SPLITA) {
                    uint32_t al[4];
                    ldsm4(al[0], al[1], al[2], al[3],
                          st + ARR_B + aoff + t * 16 * PITCHB + kb);
#pragma unroll
                    for (int nt = 0; nt < 8; nt++) {
                        mma16816(acc[t][nt], ah, &bh[2 * nt]);
                        mma16816(acc[t][nt], al, &bh[2 * nt]);
                    }
                } else {
#pragma unroll
                    for (int nt = 0; nt < 8; nt++)
                        mma16816(acc[t][nt], ah, &bh[2 * nt]);
                }
            }
        }
        __syncthreads();
    }
    asm volatile("cp.async.wait_group 0;" ::: "memory");

    // ---- epilogue ----
    const int mrow = lane >> 2;
    const int ncol = (lane & 3) * 2;
#pragma unroll
    for (int t = 0; t < 2; t++)
#pragma unroll
        for (int nt = 0; nt < 8; nt++)
#pragma unroll
            for (int hp = 0; hp < 2; hp++) {
                int m = m0 + wm * 32 + t * 16 + mrow + hp * 8;
                int n = n0 + wn * 64 + nt * 8 + ncol;
                float v0 = acc[t][nt][hp * 2 + 0];
                float v1 = acc[t][nt][hp * 2 + 1];
                size_t off = zb * sC + (size_t)m * N + n;
                if (EPI == 0) {
                    v0 += bias[n]; v1 += bias[n + 1];
                    *(uint32_t*)(Ch + off) = pr2h(__float2half(v0), __float2half(v1));
                } else if (EPI == 1) {
                    *(uint32_t*)(Ch + off) =
                        pr2h(__float2half(v0 * alpha), __float2half(v1 * alpha));
                } else {
                    *(float2*)(Cf + off) = make_float2(v0 * alpha, v1 * alpha);
                }
            }
}

// ---------------------------------------------------------------------------
// fp32 -> (hi, lo) fp16 split, float4-vectorized
// ---------------------------------------------------------------------------
__global__ void split_kernel(const float* __restrict__ x,
                             __half* __restrict__ h, __half* __restrict__ l,
                             size_t n4)
{
    size_t i  = (size_t)blockIdx.x * blockDim.x + threadIdx.x;
    size_t st = (size_t)gridDim.x * blockDim.x;
    for (; i < n4; i += st) {
        float4 v = ((const float4*)x)[i];
        __half h0, l0, h1, l1, h2, l2, h3, l3;
        splith(v.x, h0, l0); splith(v.y, h1, l1);
        splith(v.z, h2, l2); splith(v.w, h3, l3);
        ((uint2*)h)[i] = make_uint2(pr2h(h0, h1), pr2h(h2, h3));
        ((uint2*)l)[i] = make_uint2(pr2h(l0, l1), pr2h(l2, l3));
    }
}

// fp32 -> fp16 convert (B operands need no lo part)
__global__ void conv_kernel(const float* __restrict__ x,
                            __half* __restrict__ h, size_t n4)
{
    size_t i  = (size_t)blockIdx.x * blockDim.x + threadIdx.x;
    size_t st = (size_t)gridDim.x * blockDim.x;
    for (; i < n4; i += st) {
        float4 v = ((const float4*)x)[i];
        ((uint2*)h)[i] = make_uint2(
            pr2h(__float2half(v.x), __float2half(v.y)),
            pr2h(__float2half(v.z), __float2half(v.w)));
    }
}

// ---------------------------------------------------------------------------
// 32x32 tiled fp16 transpose: [b][SEQ][DIM] -> [b][DIM][SEQ]
// ---------------------------------------------------------------------------
__global__ void transpose_kernel(const __half* __restrict__ in,
                                 __half* __restrict__ out)
{
    __shared__ __half t[32][34];
    const size_t b = blockIdx.z;
    const __half* src = in  + b * (size_t)SEQ * DIM;
    __half*       dst = out + b * (size_t)SEQ * DIM;
    const int s0 = blockIdx.y * 32, d0 = blockIdx.x * 32;
    const int tx = threadIdx.x & 31, ty = threadIdx.x >> 5;
#pragma unroll
    for (int i = 0; i < 4; i++)
        t[ty + i * 8][tx] = src[(size_t)(s0 + ty + i * 8) * DIM + d0 + tx];
    __syncthreads();
#pragma unroll
    for (int i = 0; i < 4; i++)
        dst[(size_t)(d0 + ty + i * 8) * SEQ + s0 + tx] = t[tx][ty + i * 8];
}

// ---------------------------------------------------------------------------
// Row softmax over 4096-wide fp16 rows -> fp16 attention weights
// half2-vectorized: 2048 half2 per row, 8 per thread.
// ---------------------------------------------------------------------------
__global__ void __launch_bounds__(256)
softmax_kernel(const __half* __restrict__ S, __half* __restrict__ A)
{
    const __half2* p2 = (const __half2*)(S + (size_t)blockIdx.x * SEQ);
    __half2*       a2 = (__half2*)(A + (size_t)blockIdx.x * SEQ);
    const int t = threadIdx.x;

    float2 v[8];
    float m = -1e30f;
#pragma unroll
    for (int i = 0; i < 8; i++) {
        v[i] = __half22float2(p2[t + 256 * i]);
        m = fmaxf(m, fmaxf(v[i].x, v[i].y));
    }
    __shared__ float redmax[8], redsum[8];
#pragma unroll
    for (int o = 16; o > 0; o >>= 1)
        m = fmaxf(m, __shfl_xor_sync(0xffffffffu, m, o));
    if ((t & 31) == 0) redmax[t >> 5] = m;
    __syncthreads();
    m = redmax[0];
#pragma unroll
    for (int w = 1; w < 8; w++) m = fmaxf(m, redmax[w]);

    float sum = 0.0f;
#pragma unroll
    for (int i = 0; i < 8; i++) {
        v[i].x = __expf(v[i].x - m);
        v[i].y = __expf(v[i].y - m);
        sum += v[i].x + v[i].y;
    }
#pragma unroll
    for (int o = 16; o > 0; o >>= 1)
        sum += __shfl_xor_sync(0xffffffffu, sum, o);
    if ((t & 31) == 0) redsum[t >> 5] = sum;
    __syncthreads();
    sum = 0.0f;
#pragma unroll
    for (int w = 0; w < 8; w++) sum += redsum[w];

    const float inv = 1.0f / sum;
#pragma unroll
    for (int i = 0; i < 8; i++)
        a2[t + 256 * i] = __floats2half2_rn(v[i].x * inv, v[i].y * inv);
}

// ---------------------------------------------------------------------------
extern "C" void kernel_launch(void* const* d_in, const int* in_sizes, int n_in,
                              void* d_out, int out_size)
{
    const float* X  = (const float*)d_in[0];
    const float* Wq = (const float*)d_in[1];
    const float* bq = (const float*)d_in[2];
    const float* Wk = (const float*)d_in[3];
    const float* bk = (const float*)d_in[4];
    const float* Wv = (const float*)d_in[5];
    const float* bv = (const float*)d_in[6];
    float* out = (float*)d_out;

    __half *Xh, *Xl, *Wqp, *Wkp, *Wvp, *Q, *K, *V, *VT, *S, *A;
    cudaGetSymbolAddress((void**)&Xh,  g_Xh);  cudaGetSymbolAddress((void**)&Xl, g_Xl);
    cudaGetSymbolAddress((void**)&Wqp, g_Wq);  cudaGetSymbolAddress((void**)&Wkp, g_Wk);
    cudaGetSymbolAddress((void**)&Wvp, g_Wv);
    cudaGetSymbolAddress((void**)&Q,   g_Q);   cudaGetSymbolAddress((void**)&K,  g_K);
    cudaGetSymbolAddress((void**)&V,   g_V);   cudaGetSymbolAddress((void**)&VT, g_VT);
    cudaGetSymbolAddress((void**)&S,   g_S);   cudaGetSymbolAddress((void**)&A,  g_A);

    constexpr int SM_SPLIT  = 3 * 3 * ARR_B;   // 92160
    constexpr int SM_SINGLE = 4 * 2 * ARR_B;   // 81920
    cudaFuncSetAttribute(gemm_mma<true, 0>,  cudaFuncAttributeMaxDynamicSharedMemorySize, SM_SPLIT);
    cudaFuncSetAttribute(gemm_mma<false, 1>, cudaFuncAttributeMaxDynamicSharedMemorySize, SM_SINGLE);
    cudaFuncSetAttribute(gemm_mma<false, 2>, cudaFuncAttributeMaxDynamicSharedMemorySize, SM_SINGLE);

    // 1) operand prep: X -> hi/lo, W -> fp16
    split_kernel<<<2048, 256>>>(X, Xh, Xl, (size_t)MTOT * DIM / 4);
    conv_kernel<<<512, 256>>>(Wq, Wqp, (size_t)DIM * DIM / 4);
    conv_kernel<<<512, 256>>>(Wk, Wkp, (size_t)DIM * DIM / 4);
    conv_kernel<<<512, 256>>>(Wv, Wvp, (size_t)DIM * DIM / 4);

    // 2) projections (2-term A): q/k/v = X*W^T + b, stored single fp16
    dim3 gp(DIM / BN, MTOT / BM, 1);
    gemm_mma<true, 0><<<gp, 256, SM_SPLIT>>>(Xh, Xl, Wqp, bq, Q, nullptr,
                                             MTOT, DIM, DIM, 0, 0, 0, 1.0f);
    gemm_mma<true, 0><<<gp, 256, SM_SPLIT>>>(Xh, Xl, Wkp, bk, K, nullptr,
                                             MTOT, DIM, DIM, 0, 0, 0, 1.0f);
    gemm_mma<true, 0><<<gp, 256, SM_SPLIT>>>(Xh, Xl, Wvp, bv, V, nullptr,
                                             MTOT, DIM, DIM, 0, 0, 0, 1.0f);

    // 3) V^T for the A*V GEMM
    dim3 gt(DIM / 32, SEQ / 32, NB);
    transpose_kernel<<<gt, 256>>>(V, VT);

    // 4) scores = (Q K^T) / 32 -> fp16, per batch (1-term A)
    dim3 gs(SEQ / BN, SEQ / BM, NB);
    gemm_mma<false, 1><<<gs, 256, SM_SINGLE>>>(Q, nullptr, K, nullptr, S, nullptr,
                                               SEQ, SEQ, DIM,
                                               (size_t)SEQ * DIM, (size_t)SEQ * DIM,
                                               (size_t)SEQ * SEQ, 1.0f / 32.0f);

    // 5) softmax -> fp16 attention weights
    softmax_kernel<<<MTOT, 256>>>(S, A);

    // 6) out = A * V   (1-term A; B = V^T [1024,4096] K-major)
    dim3 go(DIM / BN, SEQ / BM, NB);
    gemm_mma<false, 2><<<go, 256, SM_SINGLE>>>(A, nullptr, VT, nullptr, nullptr, out,
                                               SEQ, DIM, SEQ,
                                               (size_t)SEQ * SEQ, (size_t)SEQ * DIM,
                                               (size_t)SEQ * DIM, 1.0f);
}

// round 8
// speedup vs baseline: 7.2216x; 1.2073x over previous
#include <cuda_runtime.h>
#include <cuda_fp16.h>
#include <cstdint>
#include <cstddef>

#define NB  4
#define SEQ 4096
#define DIM 1024
#define MTOT (NB * SEQ)

// ---------------------------------------------------------------------------
// Scratch (static device globals; runtime allocation is forbidden)
// ---------------------------------------------------------------------------
__device__ __half g_X [(size_t)MTOT * DIM];
__device__ __half g_Wq[(size_t)DIM * DIM];
__device__ __half g_Wk[(size_t)DIM * DIM];
__device__ __half g_Wv[(size_t)DIM * DIM];
__device__ __half g_Q [(size_t)MTOT * DIM];
__device__ __half g_K [(size_t)MTOT * DIM];
__device__ __half g_V [(size_t)MTOT * DIM];
__device__ __half g_VT[(size_t)MTOT * DIM];
__device__ __half g_S [(size_t)NB * SEQ * SEQ];
__device__ __half g_A [(size_t)NB * SEQ * SEQ];

// ---------------------------------------------------------------------------
// PTX helpers
// ---------------------------------------------------------------------------
__device__ __forceinline__ uint32_t s2u(const void* p) {
    uint32_t a;
    asm("{ .reg .u64 t; cvta.to.shared.u64 t, %1; cvt.u32.u64 %0, t; }"
        : "=r"(a) : "l"(p));
    return a;
}
__device__ __forceinline__ void cpasync16(uint32_t s, const void* g) {
    asm volatile("cp.async.cg.shared.global [%0], [%1], 16;"
                 :: "r"(s), "l"(g) : "memory");
}
__device__ __forceinline__ void cp_commit() {
    asm volatile("cp.async.commit_group;" ::: "memory");
}
__device__ __forceinline__ void ldsm4(uint32_t& r0, uint32_t& r1,
                                      uint32_t& r2, uint32_t& r3, uint32_t a) {
    asm volatile("ldmatrix.sync.aligned.m8n8.x4.shared.b16 {%0,%1,%2,%3}, [%4];"
                 : "=r"(r0), "=r"(r1), "=r"(r2), "=r"(r3) : "r"(a));
}
__device__ __forceinline__ void mma16816(float* c, const uint32_t* a,
                                         const uint32_t* b) {
    asm volatile(
        "mma.sync.aligned.m16n8k16.row.col.f32.f16.f16.f32 "
        "{%0,%1,%2,%3}, {%4,%5,%6,%7}, {%8,%9}, {%0,%1,%2,%3};"
        : "+f"(c[0]), "+f"(c[1]), "+f"(c[2]), "+f"(c[3])
        : "r"(a[0]), "r"(a[1]), "r"(a[2]), "r"(a[3]), "r"(b[0]), "r"(b[1]));
}
__device__ __forceinline__ uint32_t pr2h(__half a, __half b) {
    return ((uint32_t)__half_as_ushort(b) << 16) | __half_as_ushort(a);
}

// ---------------------------------------------------------------------------
// fp16 GEMM:  C[M,N] = A[M,K] * (B[N,K])^T
// 128 threads (4 warps, 2x2), CTA tile 128x128x32, warp tile 64x64.
// cp.async 4-stage pipeline, 2 CTAs/SM, one __syncthreads per slab.
// EPI 0: +bias -> fp16.  EPI 1: *alpha -> fp16.  EPI 2: *alpha -> fp32.
// SMEM/stage: A,B each 128 rows x 80 B (64 data + 16 pad); stage 20480 B,
// 4 stages = 81920 B. ldmatrix conflict-free (verified layout from r3-r7).
// ---------------------------------------------------------------------------
constexpr int BM = 128, BN = 128, BK = 32;
constexpr int PITCHB  = 80;
constexpr int ARR_B   = 128 * PITCHB;   // 10240
constexpr int STAGE_B = 2 * ARR_B;      // 20480
constexpr int SMEM_TOTAL = 4 * STAGE_B; // 81920

template <int EPI>
__global__ void __launch_bounds__(128, 2)
gemm_mma(const __half* __restrict__ Ag, const __half* __restrict__ Bg,
         const float* __restrict__ bias,
         __half* __restrict__ Ch, float* __restrict__ Cf,
         int M, int N, int K,
         size_t sA, size_t sB, size_t sC, float alpha)
{
    extern __shared__ char smem[];
    const int tid  = threadIdx.x;
    const int lane = tid & 31, warp = tid >> 5;
    const int wm = warp >> 1, wn = warp & 1;           // 2x2 grid of 64x64
    const int m0 = blockIdx.y * BM, n0 = blockIdx.x * BN;
    const size_t zb = blockIdx.z;

    const __half* A = Ag + zb * sA;
    const __half* B = Bg + zb * sB;

    const uint32_t sbase = s2u(smem);

    // ---- per-thread cp.async slots: 8 x 16B per slab (A:4, B:4) ----
    const __half* gsrc[8];
    uint32_t soff[8];
#pragma unroll
    for (int j = 0; j < 8; j++) {
        int a   = j >> 2;                    // 0:A 1:B
        int cia = ((j & 3) << 7) | tid;      // 0..511
        int row = cia >> 2, c16 = cia & 3;
        const __half* bp = a ? B : A;
        int r0 = a ? n0 : m0;
        gsrc[j] = bp + (size_t)(r0 + row) * K + c16 * 8;
        soff[j] = a * ARR_B + row * PITCHB + c16 * 16;
    }

    const int NS = K / BK;

    auto issue = [&](int slab) {
        uint32_t st = sbase + (slab & 3) * STAGE_B;
#pragma unroll
        for (int j = 0; j < 8; j++)
            cpasync16(st + soff[j], gsrc[j] + slab * BK);
    };

    issue(0); cp_commit();
    issue(1); cp_commit();
    issue(2); cp_commit();

    float acc[4][8][4];
#pragma unroll
    for (int t = 0; t < 4; t++)
#pragma unroll
        for (int nt = 0; nt < 8; nt++)
#pragma unroll
            for (int f = 0; f < 4; f++) acc[t][nt][f] = 0.0f;

    // ldmatrix relative offsets (same verified pattern as r3-r7)
    const uint32_t aoff = (uint32_t)((wm * 64 + (lane & 15)) * PITCHB +
                                     ((lane >> 4) << 4));
    const uint32_t boff = (uint32_t)((wn * 64 + ((lane >> 4) << 3) + (lane & 7)) * PITCHB +
                                     (((lane >> 3) & 1) << 4));

    for (int s = 0; s < NS; s++) {
        asm volatile("cp.async.wait_group 2;" ::: "memory");
        __syncthreads();
        if (s + 3 < NS) issue(s + 3);
        cp_commit();

        const uint32_t st = sbase + (s & 3) * STAGE_B;
#pragma unroll
        for (int kk = 0; kk < 2; kk++) {
            const uint32_t kb = kk * 32;     // 16 halves = 32 bytes
            uint32_t bh[16];
#pragma unroll
            for (int p = 0; p < 4; p++)
                ldsm4(bh[4*p], bh[4*p+1], bh[4*p+2], bh[4*p+3],
                      st + ARR_B + boff + p * 16 * PITCHB + kb);
#pragma unroll
            for (int t = 0; t < 4; t++) {
                uint32_t ah[4];
                ldsm4(ah[0], ah[1], ah[2], ah[3],
                      st + aoff + t * 16 * PITCHB + kb);
#pragma unroll
                for (int nt = 0; nt < 8; nt++)
                    mma16816(acc[t][nt], ah, &bh[2 * nt]);
            }
        }
    }
    asm volatile("cp.async.wait_group 0;" ::: "memory");

    // ---- epilogue ----
    const int mrow = lane >> 2;
    const int ncol = (lane & 3) * 2;
#pragma unroll
    for (int t = 0; t < 4; t++)
#pragma unroll
        for (int nt = 0; nt < 8; nt++)
#pragma unroll
            for (int hp = 0; hp < 2; hp++) {
                int m = m0 + wm * 64 + t * 16 + mrow + hp * 8;
                int n = n0 + wn * 64 + nt * 8 + ncol;
                float v0 = acc[t][nt][hp * 2 + 0];
                float v1 = acc[t][nt][hp * 2 + 1];
                size_t off = zb * sC + (size_t)m * N + n;
                if (EPI == 0) {
                    v0 += bias[n]; v1 += bias[n + 1];
                    *(uint32_t*)(Ch + off) = pr2h(__float2half(v0), __float2half(v1));
                } else if (EPI == 1) {
                    *(uint32_t*)(Ch + off) =
                        pr2h(__float2half(v0 * alpha), __float2half(v1 * alpha));
                } else {
                    *(float2*)(Cf + off) = make_float2(v0 * alpha, v1 * alpha);
                }
            }
}

// ---------------------------------------------------------------------------
// fp32 -> fp16 convert, float4-vectorized
// ---------------------------------------------------------------------------
__global__ void conv_kernel(const float* __restrict__ x,
                            __half* __restrict__ h, size_t n4)
{
    size_t i  = (size_t)blockIdx.x * blockDim.x + threadIdx.x;
    size_t st = (size_t)gridDim.x * blockDim.x;
    for (; i < n4; i += st) {
        float4 v = ((const float4*)x)[i];
        ((uint2*)h)[i] = make_uint2(
            pr2h(__float2half(v.x), __float2half(v.y)),
            pr2h(__float2half(v.z), __float2half(v.w)));
    }
}

// ---------------------------------------------------------------------------
// 32x32 tiled fp16 transpose: [b][SEQ][DIM] -> [b][DIM][SEQ]
// ---------------------------------------------------------------------------
__global__ void transpose_kernel(const __half* __restrict__ in,
                                 __half* __restrict__ out)
{
    __shared__ __half t[32][34];
    const size_t b = blockIdx.z;
    const __half* src = in  + b * (size_t)SEQ * DIM;
    __half*       dst = out + b * (size_t)SEQ * DIM;
    const int s0 = blockIdx.y * 32, d0 = blockIdx.x * 32;
    const int tx = threadIdx.x & 31, ty = threadIdx.x >> 5;
#pragma unroll
    for (int i = 0; i < 4; i++)
        t[ty + i * 8][tx] = src[(size_t)(s0 + ty + i * 8) * DIM + d0 + tx];
    __syncthreads();
#pragma unroll
    for (int i = 0; i < 4; i++)
        dst[(size_t)(d0 + ty + i * 8) * SEQ + s0 + tx] = t[tx][ty + i * 8];
}

// ---------------------------------------------------------------------------
// Row softmax over 4096-wide fp16 rows -> fp16 attention weights
// ---------------------------------------------------------------------------
__global__ void __launch_bounds__(256)
softmax_kernel(const __half* __restrict__ S, __half* __restrict__ A)
{
    const __half2* p2 = (const __half2*)(S + (size_t)blockIdx.x * SEQ);
    __half2*       a2 = (__half2*)(A + (size_t)blockIdx.x * SEQ);
    const int t = threadIdx.x;

    float2 v[8];
    float m = -1e30f;
#pragma unroll
    for (int i = 0; i < 8; i++) {
        v[i] = __half22float2(p2[t + 256 * i]);
        m = fmaxf(m, fmaxf(v[i].x, v[i].y));
    }
    __shared__ float redmax[8], redsum[8];
#pragma unroll
    for (int o = 16; o > 0; o >>= 1)
        m = fmaxf(m, __shfl_xor_sync(0xffffffffu, m, o));
    if ((t & 31) == 0) redmax[t >> 5] = m;
    __syncthreads();
    m = redmax[0];
#pragma unroll
    for (int w = 1; w < 8; w++) m = fmaxf(m, redmax[w]);

    float sum = 0.0f;
#pragma unroll
    for (int i = 0; i < 8; i++) {
        v[i].x = __expf(v[i].x - m);
        v[i].y = __expf(v[i].y - m);
        sum += v[i].x + v[i].y;
    }
#pragma unroll
    for (int o = 16; o > 0; o >>= 1)
        sum += __shfl_xor_sync(0xffffffffu, sum, o);
    if ((t & 31) == 0) redsum[t >> 5] = sum;
    __syncthreads();
    sum = 0.0f;
#pragma unroll
    for (int w = 0; w < 8; w++) sum += redsum[w];

    const float inv = 1.0f / sum;
#pragma unroll
    for (int i = 0; i < 8; i++)
        a2[t + 256 * i] = __floats2half2_rn(v[i].x * inv, v[i].y * inv);
}

// ---------------------------------------------------------------------------
extern "C" void kernel_launch(void* const* d_in, const int* in_sizes, int n_in,
                              void* d_out, int out_size)
{
    const float* X  = (const float*)d_in[0];
    const float* Wq = (const float*)d_in[1];
    const float* bq = (const float*)d_in[2];
    const float* Wk = (const float*)d_in[3];
    const float* bk = (const float*)d_in[4];
    const float* Wv = (const float*)d_in[5];
    const float* bv = (const float*)d_in[6];
    float* out = (float*)d_out;

    __half *Xp, *Wqp, *Wkp, *Wvp, *Q, *K, *V, *VT, *S, *A;
    cudaGetSymbolAddress((void**)&Xp,  g_X);
    cudaGetSymbolAddress((void**)&Wqp, g_Wq);  cudaGetSymbolAddress((void**)&Wkp, g_Wk);
    cudaGetSymbolAddress((void**)&Wvp, g_Wv);
    cudaGetSymbolAddress((void**)&Q,   g_Q);   cudaGetSymbolAddress((void**)&K,  g_K);
    cudaGetSymbolAddress((void**)&V,   g_V);   cudaGetSymbolAddress((void**)&VT, g_VT);
    cudaGetSymbolAddress((void**)&S,   g_S);   cudaGetSymbolAddress((void**)&A,  g_A);

    cudaFuncSetAttribute(gemm_mma<0>, cudaFuncAttributeMaxDynamicSharedMemorySize, SMEM_TOTAL);
    cudaFuncSetAttribute(gemm_mma<1>, cudaFuncAttributeMaxDynamicSharedMemorySize, SMEM_TOTAL);
    cudaFuncSetAttribute(gemm_mma<2>, cudaFuncAttributeMaxDynamicSharedMemorySize, SMEM_TOTAL);

    // 1) operand prep: everything -> fp16
    conv_kernel<<<2048, 256>>>(X,  Xp,  (size_t)MTOT * DIM / 4);
    conv_kernel<<<512,  256>>>(Wq, Wqp, (size_t)DIM * DIM / 4);
    conv_kernel<<<512,  256>>>(Wk, Wkp, (size_t)DIM * DIM / 4);
    conv_kernel<<<512,  256>>>(Wv, Wvp, (size_t)DIM * DIM / 4);

    // 2) projections: q/k/v = X*W^T + b -> fp16
    dim3 gp(DIM / BN, MTOT / BM, 1);
    gemm_mma<0><<<gp, 128, SMEM_TOTAL>>>(Xp, Wqp, bq, Q, nullptr,
                                         MTOT, DIM, DIM, 0, 0, 0, 1.0f);
    gemm_mma<0><<<gp, 128, SMEM_TOTAL>>>(Xp, Wkp, bk, K, nullptr,
                                         MTOT, DIM, DIM, 0, 0, 0, 1.0f);
    gemm_mma<0><<<gp, 128, SMEM_TOTAL>>>(Xp, Wvp, bv, V, nullptr,
                                         MTOT, DIM, DIM, 0, 0, 0, 1.0f);

    // 3) V^T for the A*V GEMM
    dim3 gt(DIM / 32, SEQ / 32, NB);
    transpose_kernel<<<gt, 256>>>(V, VT);

    // 4) scores = (Q K^T) / 32 -> fp16, per batch
    dim3 gs(SEQ / BN, SEQ / BM, NB);
    gemm_mma<1><<<gs, 128, SMEM_TOTAL>>>(Q, K, nullptr, S, nullptr,
                                         SEQ, SEQ, DIM,
                                         (size_t)SEQ * DIM, (size_t)SEQ * DIM,
                                         (size_t)SEQ * SEQ, 1.0f / 32.0f);

    // 5) softmax -> fp16 attention weights
    softmax_kernel<<<MTOT, 256>>>(S, A);

    // 6) out = A * V   (B = V^T [1024,4096] K-major)
    dim3 go(DIM / BN, SEQ / BM, NB);
    gemm_mma<2><<<go, 128, SMEM_TOTAL>>>(A, VT, nullptr, nullptr, out,
                                         SEQ, DIM, SEQ,
                                         (size_t)SEQ * SEQ, (size_t)SEQ * DIM,
                                         (size_t)SEQ * DIM, 1.0f);
}

// round 9
// speedup vs baseline: 7.3789x; 1.0218x over previous
#include <cuda_runtime.h>
#include <cuda_fp16.h>
#include <cstdint>
#include <cstddef>

#define NB  4
#define SEQ 4096
#define DIM 1024
#define MTOT (NB * SEQ)

// ---------------------------------------------------------------------------
// Scratch (static device globals; runtime allocation is forbidden)
// ---------------------------------------------------------------------------
__device__ __half g_X [(size_t)MTOT * DIM];
__device__ __half g_Wq[(size_t)DIM * DIM];
__device__ __half g_Wk[(size_t)DIM * DIM];
__device__ __half g_Wv[(size_t)DIM * DIM];
__device__ __half g_Q [(size_t)MTOT * DIM];
__device__ __half g_K [(size_t)MTOT * DIM];
__device__ __half g_V [(size_t)MTOT * DIM];
__device__ __half g_S [(size_t)NB * SEQ * SEQ];
__device__ __half g_A [(size_t)NB * SEQ * SEQ];

// ---------------------------------------------------------------------------
// PTX helpers
// ---------------------------------------------------------------------------
__device__ __forceinline__ uint32_t s2u(const void* p) {
    uint32_t a;
    asm("{ .reg .u64 t; cvta.to.shared.u64 t, %1; cvt.u32.u64 %0, t; }"
        : "=r"(a) : "l"(p));
    return a;
}
__device__ __forceinline__ void cpasync16(uint32_t s, const void* g) {
    asm volatile("cp.async.cg.shared.global [%0], [%1], 16;"
                 :: "r"(s), "l"(g) : "memory");
}
__device__ __forceinline__ void cp_commit() {
    asm volatile("cp.async.commit_group;" ::: "memory");
}
__device__ __forceinline__ void ldsm4(uint32_t& r0, uint32_t& r1,
                                      uint32_t& r2, uint32_t& r3, uint32_t a) {
    asm volatile("ldmatrix.sync.aligned.m8n8.x4.shared.b16 {%0,%1,%2,%3}, [%4];"
                 : "=r"(r0), "=r"(r1), "=r"(r2), "=r"(r3) : "r"(a));
}
__device__ __forceinline__ void ldsm4t(uint32_t& r0, uint32_t& r1,
                                       uint32_t& r2, uint32_t& r3, uint32_t a) {
    asm volatile("ldmatrix.sync.aligned.m8n8.x4.trans.shared.b16 {%0,%1,%2,%3}, [%4];"
                 : "=r"(r0), "=r"(r1), "=r"(r2), "=r"(r3) : "r"(a));
}
__device__ __forceinline__ void mma16816(float* c, const uint32_t* a,
                                         const uint32_t* b) {
    asm volatile(
        "mma.sync.aligned.m16n8k16.row.col.f32.f16.f16.f32 "
        "{%0,%1,%2,%3}, {%4,%5,%6,%7}, {%8,%9}, {%0,%1,%2,%3};"
        : "+f"(c[0]), "+f"(c[1]), "+f"(c[2]), "+f"(c[3])
        : "r"(a[0]), "r"(a[1]), "r"(a[2]), "r"(a[3]), "r"(b[0]), "r"(b[1]));
}
__device__ __forceinline__ uint32_t pr2h(__half a, __half b) {
    return ((uint32_t)__half_as_ushort(b) << 16) | __half_as_ushort(a);
}

// ---------------------------------------------------------------------------
// fp16 GEMM:  C[M,N] = A[M,K] * op(B)
// BTRANS=false: B stored [N][K] row-major (C = A*B^T), ldmatrix non-trans.
// BTRANS=true : B stored [K][N] row-major (C = A*B),   ldmatrix.trans.
// 128 threads (4 warps, 2x2), CTA tile 128x128, K slab 64, warp tile 64x64.
// cp.async 3-stage pipeline (36 KB/stage), 2 CTAs/SM, fragment double-buffer.
// EPI 0: +bias -> fp16.  EPI 1: *alpha -> fp16.  EPI 2: *alpha -> fp32.
// ---------------------------------------------------------------------------
constexpr int BM = 128, BN = 128, BK = 64;
constexpr int PITCH_A  = 144;               // 128 B data + 16 pad
constexpr int ARR_A    = 128 * PITCH_A;     // 18432
constexpr int PITCH_BT = 272;               // 256 B data + 16 pad
constexpr int ARR_BT   = 64 * PITCH_BT;     // 17408
constexpr int SM_STD = 3 * (ARR_A + ARR_A);   // 110592
constexpr int SM_TRN = 3 * (ARR_A + ARR_BT);  // 107520

template <int EPI, bool BTRANS>
__global__ void __launch_bounds__(128, 2)
gemm_mma(const __half* __restrict__ Ag, const __half* __restrict__ Bg,
         const float* __restrict__ bias,
         __half* __restrict__ Ch, float* __restrict__ Cf,
         int N, int K, int Ng,
         size_t sA, size_t sB, size_t sC, float alpha)
{
    constexpr int ARRB  = BTRANS ? ARR_BT : ARR_A;
    constexpr int STAGE = ARR_A + ARRB;

    extern __shared__ char smem[];
    const int tid  = threadIdx.x;
    const int lane = tid & 31, warp = tid >> 5;
    const int wm = warp >> 1, wn = warp & 1;
    const int m0 = blockIdx.y * BM, n0 = blockIdx.x * BN;
    const size_t zb = blockIdx.z;

    const __half* A = Ag + zb * sA;
    const __half* B = Bg + zb * sB;
    const uint32_t sbase = s2u(smem);

    // ---- cp.async per-thread bases (8 slots each for A and B) ----
    const __half* gA = A + (size_t)(m0 + (tid >> 3)) * K + (tid & 7) * 8;
    const uint32_t sA0 = (tid >> 3) * PITCH_A + (tid & 7) * 16;
    const __half* gB;
    uint32_t sB0;
    if (BTRANS) {
        gB  = B + (size_t)(tid >> 4) * Ng + n0 + (tid & 15) * 8;
        sB0 = (tid >> 4) * PITCH_BT + (tid & 15) * 16;
    } else {
        gB  = B + (size_t)(n0 + (tid >> 3)) * K + (tid & 7) * 8;
        sB0 = (tid >> 3) * PITCH_A + (tid & 7) * 16;
    }

    const int NS = K / BK;

    auto issue = [&](int slab) {
        const uint32_t st = sbase + (slab % 3) * STAGE;
        const __half* ga = gA + (size_t)slab * BK;
#pragma unroll
        for (int j = 0; j < 8; j++)
            cpasync16(st + sA0 + j * (16 * PITCH_A), ga + (size_t)j * 16 * K);
        if (BTRANS) {
            const __half* gb = gB + (size_t)slab * BK * Ng;
#pragma unroll
            for (int j = 0; j < 8; j++)
                cpasync16(st + ARR_A + sB0 + j * (8 * PITCH_BT),
                          gb + (size_t)j * 8 * Ng);
        } else {
            const __half* gb = gB + (size_t)slab * BK;
#pragma unroll
            for (int j = 0; j < 8; j++)
                cpasync16(st + ARR_A + sB0 + j * (16 * PITCH_A),
                          gb + (size_t)j * 16 * K);
        }
    };

    issue(0); cp_commit();
    issue(1); cp_commit();

    float acc[4][8][4];
#pragma unroll
    for (int t = 0; t < 4; t++)
#pragma unroll
        for (int nt = 0; nt < 8; nt++)
#pragma unroll
            for (int f = 0; f < 4; f++) acc[t][nt][f] = 0.0f;

    // ldmatrix offsets
    const uint32_t aoff = (uint32_t)((wm * 64 + (lane & 15)) * PITCH_A +
                                     ((lane >> 4) << 4));
    uint32_t boff;
    if (BTRANS)
        boff = (uint32_t)(((((lane >> 3) & 1) << 3) + (lane & 7)) * PITCH_BT +
                          ((lane >> 4) << 4) + wn * 128);
    else
        boff = (uint32_t)((wn * 64 + ((lane >> 4) << 3) + (lane & 7)) * PITCH_A +
                          (((lane >> 3) & 1) << 4));

    auto ldB = [&](uint32_t* b, uint32_t st, int kk) {
#pragma unroll
        for (int p = 0; p < 4; p++) {
            if (BTRANS)
                ldsm4t(b[4*p], b[4*p+1], b[4*p+2], b[4*p+3],
                       st + ARR_A + boff + kk * (16 * PITCH_BT) + p * 32);
            else
                ldsm4(b[4*p], b[4*p+1], b[4*p+2], b[4*p+3],
                      st + ARR_A + boff + kk * 32 + p * (16 * PITCH_A));
        }
    };

    for (int s = 0; s < NS; s++) {
        asm volatile("cp.async.wait_group 1;" ::: "memory");
        __syncthreads();
        if (s + 2 < NS) issue(s + 2);
        cp_commit();

        const uint32_t st = sbase + (s % 3) * STAGE;
        uint32_t bh[2][16], ap[2][4];
        ldB(bh[0], st, 0);
        ldsm4(ap[0][0], ap[0][1], ap[0][2], ap[0][3], st + aoff);  // kk=0, t=0
#pragma unroll
        for (int kk = 0; kk < 4; kk++) {
            const int cur = kk & 1;
            if (kk < 3) {      // prefetch next kk's B frags + first A frag
                ldB(bh[cur ^ 1], st, kk + 1);
                ldsm4(ap[cur ^ 1][0], ap[cur ^ 1][1], ap[cur ^ 1][2], ap[cur ^ 1][3],
                      st + aoff + (kk + 1) * 32);
            }
#pragma unroll
            for (int t = 0; t < 4; t++) {
                uint32_t ah[4];
                if (t == 0) {
                    ah[0] = ap[cur][0]; ah[1] = ap[cur][1];
                    ah[2] = ap[cur][2]; ah[3] = ap[cur][3];
                } else {
                    ldsm4(ah[0], ah[1], ah[2], ah[3],
                          st + aoff + t * (16 * PITCH_A) + kk * 32);
                }
#pragma unroll
                for (int nt = 0; nt < 8; nt++)
                    mma16816(acc[t][nt], ah, &bh[cur][2 * nt]);
            }
        }
    }
    asm volatile("cp.async.wait_group 0;" ::: "memory");

    // ---- epilogue ----
    const int mrow = lane >> 2;
    const int ncol = (lane & 3) * 2;
#pragma unroll
    for (int t = 0; t < 4; t++)
#pragma unroll
        for (int nt = 0; nt < 8; nt++)
#pragma unroll
            for (int hp = 0; hp < 2; hp++) {
                int m = m0 + wm * 64 + t * 16 + mrow + hp * 8;
                int n = n0 + wn * 64 + nt * 8 + ncol;
                float v0 = acc[t][nt][hp * 2 + 0];
                float v1 = acc[t][nt][hp * 2 + 1];
                size_t off = zb * sC + (size_t)m * N + n;
                if (EPI == 0) {
                    v0 += bias[n]; v1 += bias[n + 1];
                    *(uint32_t*)(Ch + off) = pr2h(__float2half(v0), __float2half(v1));
                } else if (EPI == 1) {
                    *(uint32_t*)(Ch + off) =
                        pr2h(__float2half(v0 * alpha), __float2half(v1 * alpha));
                } else {
                    *(float2*)(Cf + off) = make_float2(v0 * alpha, v1 * alpha);
                }
            }
}

// ---------------------------------------------------------------------------
// fp32 -> fp16 convert, float4-vectorized
// ---------------------------------------------------------------------------
__global__ void conv_kernel(const float* __restrict__ x,
                            __half* __restrict__ h, size_t n4)
{
    size_t i  = (size_t)blockIdx.x * blockDim.x + threadIdx.x;
    size_t st = (size_t)gridDim.x * blockDim.x;
    for (; i < n4; i += st) {
        float4 v = ((const float4*)x)[i];
        ((uint2*)h)[i] = make_uint2(
            pr2h(__float2half(v.x), __float2half(v.y)),
            pr2h(__float2half(v.z), __float2half(v.w)));
    }
}

// ---------------------------------------------------------------------------
// Row softmax over 4096-wide fp16 rows -> fp16 attention weights
// ---------------------------------------------------------------------------
__global__ void __launch_bounds__(256)
softmax_kernel(const __half* __restrict__ S, __half* __restrict__ A)
{
    const __half2* p2 = (const __half2*)(S + (size_t)blockIdx.x * SEQ);
    __half2*       a2 = (__half2*)(A + (size_t)blockIdx.x * SEQ);
    const int t = threadIdx.x;

    float2 v[8];
    float m = -1e30f;
#pragma unroll
    for (int i = 0; i < 8; i++) {
        v[i] = __half22float2(p2[t + 256 * i]);
        m = fmaxf(m, fmaxf(v[i].x, v[i].y));
    }
    __shared__ float redmax[8], redsum[8];
#pragma unroll
    for (int o = 16; o > 0; o >>= 1)
        m = fmaxf(m, __shfl_xor_sync(0xffffffffu, m, o));
    if ((t & 31) == 0) redmax[t >> 5] = m;
    __syncthreads();
    m = redmax[0];
#pragma unroll
    for (int w = 1; w < 8; w++) m = fmaxf(m, redmax[w]);

    float sum = 0.0f;
#pragma unroll
    for (int i = 0; i < 8; i++) {
        v[i].x = __expf(v[i].x - m);
        v[i].y = __expf(v[i].y - m);
        sum += v[i].x + v[i].y;
    }
#pragma unroll
    for (int o = 16; o > 0; o >>= 1)
        sum += __shfl_xor_sync(0xffffffffu, sum, o);
    if ((t & 31) == 0) redsum[t >> 5] = sum;
    __syncthreads();
    sum = 0.0f;
#pragma unroll
    for (int w = 0; w < 8; w++) sum += redsum[w];

    const float inv = 1.0f / sum;
#pragma unroll
    for (int i = 0; i < 8; i++)
        a2[t + 256 * i] = __floats2half2_rn(v[i].x * inv, v[i].y * inv);
}

// ---------------------------------------------------------------------------
extern "C" void kernel_launch(void* const* d_in, const int* in_sizes, int n_in,
                              void* d_out, int out_size)
{
    const float* X  = (const float*)d_in[0];
    const float* Wq = (const float*)d_in[1];
    const float* bq = (const float*)d_in[2];
    const float* Wk = (const float*)d_in[3];
    const float* bk = (const float*)d_in[4];
    const float* Wv = (const float*)d_in[5];
    const float* bv = (const float*)d_in[6];
    float* out = (float*)d_out;

    __half *Xp, *Wqp, *Wkp, *Wvp, *Q, *K, *V, *S, *A;
    cudaGetSymbolAddress((void**)&Xp,  g_X);
    cudaGetSymbolAddress((void**)&Wqp, g_Wq);  cudaGetSymbolAddress((void**)&Wkp, g_Wk);
    cudaGetSymbolAddress((void**)&Wvp, g_Wv);
    cudaGetSymbolAddress((void**)&Q,   g_Q);   cudaGetSymbolAddress((void**)&K,  g_K);
    cudaGetSymbolAddress((void**)&V,   g_V);
    cudaGetSymbolAddress((void**)&S,   g_S);   cudaGetSymbolAddress((void**)&A,  g_A);

    cudaFuncSetAttribute(gemm_mma<0, false>, cudaFuncAttributeMaxDynamicSharedMemorySize, SM_STD);
    cudaFuncSetAttribute(gemm_mma<1, false>, cudaFuncAttributeMaxDynamicSharedMemorySize, SM_STD);
    cudaFuncSetAttribute(gemm_mma<2, true>,  cudaFuncAttributeMaxDynamicSharedMemorySize, SM_TRN);

    // 1) operand prep: everything -> fp16
    conv_kernel<<<2048, 256>>>(X,  Xp,  (size_t)MTOT * DIM / 4);
    conv_kernel<<<512,  256>>>(Wq, Wqp, (size_t)DIM * DIM / 4);
    conv_kernel<<<512,  256>>>(Wk, Wkp, (size_t)DIM * DIM / 4);
    conv_kernel<<<512,  256>>>(Wv, Wvp, (size_t)DIM * DIM / 4);

    // 2) projections: q/k/v = X*W^T + b -> fp16
    dim3 gp(DIM / BN, MTOT / BM, 1);
    gemm_mma<0, false><<<gp, 128, SM_STD>>>(Xp, Wqp, bq, Q, nullptr,
                                            DIM, DIM, 0, 0, 0, 0, 1.0f);
    gemm_mma<0, false><<<gp, 128, SM_STD>>>(Xp, Wkp, bk, K, nullptr,
                                            DIM, DIM, 0, 0, 0, 0, 1.0f);
    gemm_mma<0, false><<<gp, 128, SM_STD>>>(Xp, Wvp, bv, V, nullptr,
                                            DIM, DIM, 0, 0, 0, 0, 1.0f);

    // 3) scores = (Q K^T) / 32 -> fp16, per batch
    dim3 gs(SEQ / BN, SEQ / BM, NB);
    gemm_mma<1, false><<<gs, 128, SM_STD>>>(Q, K, nullptr, S, nullptr,
                                            SEQ, DIM, 0,
                                            (size_t)SEQ * DIM, (size_t)SEQ * DIM,
                                            (size_t)SEQ * SEQ, 1.0f / 32.0f);

    // 4) softmax -> fp16 attention weights
    softmax_kernel<<<MTOT, 256>>>(S, A);

    // 5) out = A * V  (B = V row-major [SEQ][DIM], trans-loaded)
    dim3 go(DIM / BN, SEQ / BM, NB);
    gemm_mma<2, true><<<go, 128, SM_TRN>>>(A, V, nullptr, nullptr, out,
                                           DIM, SEQ, DIM,
                                           (size_t)SEQ * SEQ, (size_t)SEQ * DIM,
                                           (size_t)SEQ * DIM, 1.0f);
}

// round 12
// speedup vs baseline: 7.4866x; 1.0146x over previous
#include <cuda_runtime.h>
#include <cuda_fp16.h>
#include <cstdint>
#include <cstddef>

#define NB  4
#define SEQ 4096
#define DIM 1024
#define MTOT (NB * SEQ)

// ---------------------------------------------------------------------------
// Scratch (static device globals; runtime allocation is forbidden)
// ---------------------------------------------------------------------------
__device__ __half g_X [(size_t)MTOT * DIM];
__device__ __half g_Wq[(size_t)DIM * DIM];
__device__ __half g_Wk[(size_t)DIM * DIM];
__device__ __half g_Wv[(size_t)DIM * DIM];
__device__ __half g_Q [(size_t)MTOT * DIM];
__device__ __half g_K [(size_t)MTOT * DIM];
__device__ __half g_V [(size_t)MTOT * DIM];
__device__ __half g_E [(size_t)NB * SEQ * SEQ];   // exp(scores), unnormalized
__device__ float  g_RS[(size_t)MTOT];             // row sums of E

// exp(x/32) = exp2(x * (1/32) * log2(e))
#define EXP_SCALE 0.045083183f

// ---------------------------------------------------------------------------
// PTX helpers
// ---------------------------------------------------------------------------
__device__ __forceinline__ uint32_t s2u(const void* p) {
    uint32_t a;
    asm("{ .reg .u64 t; cvta.to.shared.u64 t, %1; cvt.u32.u64 %0, t; }"
        : "=r"(a) : "l"(p));
    return a;
}
__device__ __forceinline__ void cpasync16(uint32_t s, const void* g) {
    asm volatile("cp.async.cg.shared.global [%0], [%1], 16;"
                 :: "r"(s), "l"(g) : "memory");
}
__device__ __forceinline__ void cp_commit() {
    asm volatile("cp.async.commit_group;" ::: "memory");
}
__device__ __forceinline__ void ldsm4(uint32_t& r0, uint32_t& r1,
                                      uint32_t& r2, uint32_t& r3, uint32_t a) {
    asm volatile("ldmatrix.sync.aligned.m8n8.x4.shared.b16 {%0,%1,%2,%3}, [%4];"
                 : "=r"(r0), "=r"(r1), "=r"(r2), "=r"(r3) : "r"(a));
}
__device__ __forceinline__ void ldsm4t(uint32_t& r0, uint32_t& r1,
                                       uint32_t& r2, uint32_t& r3, uint32_t a) {
    asm volatile("ldmatrix.sync.aligned.m8n8.x4.trans.shared.b16 {%0,%1,%2,%3}, [%4];"
                 : "=r"(r0), "=r"(r1), "=r"(r2), "=r"(r3) : "r"(a));
}
__device__ __forceinline__ void mma16816(float* c, const uint32_t* a,
                                         const uint32_t* b) {
    asm volatile(
        "mma.sync.aligned.m16n8k16.row.col.f32.f16.f16.f32 "
        "{%0,%1,%2,%3}, {%4,%5,%6,%7}, {%8,%9}, {%0,%1,%2,%3};"
        : "+f"(c[0]), "+f"(c[1]), "+f"(c[2]), "+f"(c[3])
        : "r"(a[0]), "r"(a[1]), "r"(a[2]), "r"(a[3]), "r"(b[0]), "r"(b[1]));
}
__device__ __forceinline__ uint32_t pr2h(__half a, __half b) {
    return ((uint32_t)__half_as_ushort(b) << 16) | __half_as_ushort(a);
}

// ---------------------------------------------------------------------------
// fp16 GEMM:  C[M,N] = A[M,K] * op(B)
// BTRANS=false: B stored [N][K] row-major (C = A*B^T), ldmatrix non-trans.
// BTRANS=true : B stored [K][N] row-major (C = A*B),   ldmatrix.trans.
// 128 threads (4 warps, 2x2), CTA tile 128x128, K slab 64, warp tile 64x64.
// cp.async 3-stage pipeline, 2 CTAs/SM, fragment double-buffer.
// EPI 0: +bias -> fp16.
// EPI 3: exp2(acc*alpha) -> fp16           (scores; softmax numerator)
// EPI 4: acc * (1/RS[row]) -> fp32         (A*V with fused normalization)
// ---------------------------------------------------------------------------
constexpr int BM = 128, BN = 128, BK = 64;
constexpr int PITCH_A  = 144;               // 128 B data + 16 pad
constexpr int ARR_A    = 128 * PITCH_A;     // 18432
constexpr int PITCH_BT = 272;               // 256 B data + 16 pad
constexpr int ARR_BT   = 64 * PITCH_BT;     // 17408
constexpr int SM_STD = 3 * (ARR_A + ARR_A);   // 110592
constexpr int SM_TRN = 3 * (ARR_A + ARR_BT);  // 107520

template <int EPI, bool BTRANS>
__global__ void __launch_bounds__(128, 2)
gemm_mma(const __half* __restrict__ Ag, const __half* __restrict__ Bg,
         const float* __restrict__ bias, const float* __restrict__ RS,
         __half* __restrict__ Ch, float* __restrict__ Cf,
         int N, int K, int Ng,
         size_t sA, size_t sB, size_t sC, float alpha)
{
    constexpr int ARRB  = BTRANS ? ARR_BT : ARR_A;
    constexpr int STAGE = ARR_A + ARRB;

    extern __shared__ char smem[];
    const int tid  = threadIdx.x;
    const int lane = tid & 31, warp = tid >> 5;
    const int wm = warp >> 1, wn = warp & 1;
    const int m0 = blockIdx.y * BM, n0 = blockIdx.x * BN;
    const size_t zb = blockIdx.z;

    const __half* A = Ag + zb * sA;
    const __half* B = Bg + zb * sB;
    const uint32_t sbase = s2u(smem);

    // ---- cp.async per-thread bases ----
    const __half* gA = A + (size_t)(m0 + (tid >> 3)) * K + (tid & 7) * 8;
    const uint32_t sA0 = (tid >> 3) * PITCH_A + (tid & 7) * 16;
    const __half* gB;
    uint32_t sB0;
    if (BTRANS) {
        gB  = B + (size_t)(tid >> 4) * Ng + n0 + (tid & 15) * 8;
        sB0 = (tid >> 4) * PITCH_BT + (tid & 15) * 16;
    } else {
        gB  = B + (size_t)(n0 + (tid >> 3)) * K + (tid & 7) * 8;
        sB0 = (tid >> 3) * PITCH_A + (tid & 7) * 16;
    }

    const int NS = K / BK;

    auto issue = [&](int slab) {
        const uint32_t st = sbase + (slab % 3) * STAGE;
        const __half* ga = gA + (size_t)slab * BK;
#pragma unroll
        for (int j = 0; j < 8; j++)
            cpasync16(st + sA0 + j * (16 * PITCH_A), ga + (size_t)j * 16 * K);
        if (BTRANS) {
            const __half* gb = gB + (size_t)slab * BK * Ng;
#pragma unroll
            for (int j = 0; j < 8; j++)
                cpasync16(st + ARR_A + sB0 + j * (8 * PITCH_BT),
                          gb + (size_t)j * 8 * Ng);
        } else {
            const __half* gb = gB + (size_t)slab * BK;
#pragma unroll
            for (int j = 0; j < 8; j++)
                cpasync16(st + ARR_A + sB0 + j * (16 * PITCH_A),
                          gb + (size_t)j * 16 * K);
        }
    };

    issue(0); cp_commit();
    issue(1); cp_commit();

    float acc[4][8][4];
#pragma unroll
    for (int t = 0; t < 4; t++)
#pragma unroll
        for (int nt = 0; nt < 8; nt++)
#pragma unroll
            for (int f = 0; f < 4; f++) acc[t][nt][f] = 0.0f;

    const uint32_t aoff = (uint32_t)((wm * 64 + (lane & 15)) * PITCH_A +
                                     ((lane >> 4) << 4));
    uint32_t boff;
    if (BTRANS)
        boff = (uint32_t)(((((lane >> 3) & 1) << 3) + (lane & 7)) * PITCH_BT +
                          ((lane >> 4) << 4) + wn * 128);
    else
        boff = (uint32_t)((wn * 64 + ((lane >> 4) << 3) + (lane & 7)) * PITCH_A +
                          (((lane >> 3) & 1) << 4));

    auto ldB = [&](uint32_t* b, uint32_t st, int kk) {
#pragma unroll
        for (int p = 0; p < 4; p++) {
            if (BTRANS)
                ldsm4t(b[4*p], b[4*p+1], b[4*p+2], b[4*p+3],
                       st + ARR_A + boff + kk * (16 * PITCH_BT) + p * 32);
            else
                ldsm4(b[4*p], b[4*p+1], b[4*p+2], b[4*p+3],
                      st + ARR_A + boff + kk * 32 + p * (16 * PITCH_A));
        }
    };

    for (int s = 0; s < NS; s++) {
        asm volatile("cp.async.wait_group 1;" ::: "memory");
        __syncthreads();
        if (s + 2 < NS) issue(s + 2);
        cp_commit();

        const uint32_t st = sbase + (s % 3) * STAGE;
        uint32_t bh[2][16], ap[2][4];
        ldB(bh[0], st, 0);
        ldsm4(ap[0][0], ap[0][1], ap[0][2], ap[0][3], st + aoff);
#pragma unroll
        for (int kk = 0; kk < 4; kk++) {
            const int cur = kk & 1;
            if (kk < 3) {
                ldB(bh[cur ^ 1], st, kk + 1);
                ldsm4(ap[cur ^ 1][0], ap[cur ^ 1][1], ap[cur ^ 1][2], ap[cur ^ 1][3],
                      st + aoff + (kk + 1) * 32);
            }
#pragma unroll
            for (int t = 0; t < 4; t++) {
                uint32_t ah[4];
                if (t == 0) {
                    ah[0] = ap[cur][0]; ah[1] = ap[cur][1];
                    ah[2] = ap[cur][2]; ah[3] = ap[cur][3];
                } else {
                    ldsm4(ah[0], ah[1], ah[2], ah[3],
                          st + aoff + t * (16 * PITCH_A) + kk * 32);
                }
#pragma unroll
                for (int nt = 0; nt < 8; nt++)
                    mma16816(acc[t][nt], ah, &bh[cur][2 * nt]);
            }
        }
    }
    asm volatile("cp.async.wait_group 0;" ::: "memory");

    // ---- EPI 4: stage reciprocal row sums through (now idle) smem ----
    float* srs = (float*)smem;
    if (EPI == 4) {
        __syncthreads();                        // all warps past mainloop
        if (tid < 128)
            srs[tid] = 1.0f / RS[zb * SEQ + m0 + tid];
        __syncthreads();
    }

    // ---- epilogue ----
    const int mrow = lane >> 2;
    const int ncol = (lane & 3) * 2;
#pragma unroll
    for (int t = 0; t < 4; t++)
#pragma unroll
        for (int nt = 0; nt < 8; nt++)
#pragma unroll
            for (int hp = 0; hp < 2; hp++) {
                int ml = wm * 64 + t * 16 + mrow + hp * 8;   // row within CTA
                int m = m0 + ml;
                int n = n0 + wn * 64 + nt * 8 + ncol;
                float v0 = acc[t][nt][hp * 2 + 0];
                float v1 = acc[t][nt][hp * 2 + 1];
                size_t off = zb * sC + (size_t)m * N + n;
                if (EPI == 0) {
                    v0 += bias[n]; v1 += bias[n + 1];
                    *(uint32_t*)(Ch + off) = pr2h(__float2half(v0), __float2half(v1));
                } else if (EPI == 3) {
                    float e0 = exp2f(v0 * alpha);
                    float e1 = exp2f(v1 * alpha);
                    *(uint32_t*)(Ch + off) = pr2h(__float2half(e0), __float2half(e1));
                } else {
                    float inv = srs[ml];
                    *(float2*)(Cf + off) = make_float2(v0 * inv, v1 * inv);
                }
            }
}

// ---------------------------------------------------------------------------
// fp32 -> fp16 convert, float4-vectorized (single tensor)
// ---------------------------------------------------------------------------
__global__ void conv_kernel(const float* __restrict__ x,
                            __half* __restrict__ h, size_t n4)
{
    size_t i  = (size_t)blockIdx.x * blockDim.x + threadIdx.x;
    size_t st = (size_t)gridDim.x * blockDim.x;
    for (; i < n4; i += st) {
        float4 v = ((const float4*)x)[i];
        ((uint2*)h)[i] = make_uint2(
            pr2h(__float2half(v.x), __float2half(v.y)),
            pr2h(__float2half(v.z), __float2half(v.w)));
    }
}

// all three weight matrices in one launch (blockIdx.y selects tensor)
__global__ void conv3_kernel(const float* __restrict__ w0, __half* __restrict__ h0,
                             const float* __restrict__ w1, __half* __restrict__ h1,
                             const float* __restrict__ w2, __half* __restrict__ h2,
                             size_t n4)
{
    const float* x = (blockIdx.y == 0) ? w0 : (blockIdx.y == 1) ? w1 : w2;
    __half*      h = (blockIdx.y == 0) ? h0 : (blockIdx.y == 1) ? h1 : h2;
    size_t i  = (size_t)blockIdx.x * blockDim.x + threadIdx.x;
    size_t st = (size_t)gridDim.x * blockDim.x;
    for (; i < n4; i += st) {
        float4 v = ((const float4*)x)[i];
        ((uint2*)h)[i] = make_uint2(
            pr2h(__float2half(v.x), __float2half(v.y)),
            pr2h(__float2half(v.z), __float2half(v.w)));
    }
}

// ---------------------------------------------------------------------------
// Row sums of E: one block per row, deterministic fixed-order reduction.
// ---------------------------------------------------------------------------
__global__ void __launch_bounds__(256)
rowsum_kernel(const __half* __restrict__ E, float* __restrict__ RS)
{
    const __half2* p2 = (const __half2*)(E + (size_t)blockIdx.x * SEQ);
    const int t = threadIdx.x;

    float sum = 0.0f;
#pragma unroll
    for (int i = 0; i < 8; i++) {
        float2 v = __half22float2(p2[t + 256 * i]);
        sum += v.x + v.y;
    }
    __shared__ float red[8];
#pragma unroll
    for (int o = 16; o > 0; o >>= 1)
        sum += __shfl_xor_sync(0xffffffffu, sum, o);
    if ((t & 31) == 0) red[t >> 5] = sum;
    __syncthreads();
    if (t == 0) {
        float s = 0.0f;
#pragma unroll
        for (int w = 0; w < 8; w++) s += red[w];
        RS[blockIdx.x] = s;
    }
}

// ---------------------------------------------------------------------------
extern "C" void kernel_launch(void* const* d_in, const int* in_sizes, int n_in,
                              void* d_out, int out_size)
{
    const float* X  = (const float*)d_in[0];
    const float* Wq = (const float*)d_in[1];
    const float* bq = (const float*)d_in[2];
    const float* Wk = (const float*)d_in[3];
    const float* bk = (const float*)d_in[4];
    const float* Wv = (const float*)d_in[5];
    const float* bv = (const float*)d_in[6];
    float* out = (float*)d_out;

    __half *Xp, *Wqp, *Wkp, *Wvp, *Q, *K, *V, *E;
    float* RS;
    cudaGetSymbolAddress((void**)&Xp,  g_X);
    cudaGetSymbolAddress((void**)&Wqp, g_Wq);  cudaGetSymbolAddress((void**)&Wkp, g_Wk);
    cudaGetSymbolAddress((void**)&Wvp, g_Wv);
    cudaGetSymbolAddress((void**)&Q,   g_Q);   cudaGetSymbolAddress((void**)&K,  g_K);
    cudaGetSymbolAddress((void**)&V,   g_V);
    cudaGetSymbolAddress((void**)&E,   g_E);   cudaGetSymbolAddress((void**)&RS, g_RS);

    cudaFuncSetAttribute(gemm_mma<0, false>, cudaFuncAttributeMaxDynamicSharedMemorySize, SM_STD);
    cudaFuncSetAttribute(gemm_mma<3, false>, cudaFuncAttributeMaxDynamicSharedMemorySize, SM_STD);
    cudaFuncSetAttribute(gemm_mma<4, true>,  cudaFuncAttributeMaxDynamicSharedMemorySize, SM_TRN);

    // 1) operand prep -> fp16
    conv_kernel<<<2048, 256>>>(X, Xp, (size_t)MTOT * DIM / 4);
    dim3 gw(512, 3);
    conv3_kernel<<<gw, 256>>>(Wq, Wqp, Wk, Wkp, Wv, Wvp, (size_t)DIM * DIM / 4);

    // 2) projections: q/k/v = X*W^T + b -> fp16
    dim3 gp(DIM / BN, MTOT / BM, 1);
    gemm_mma<0, false><<<gp, 128, SM_STD>>>(Xp, Wqp, bq, nullptr, Q, nullptr,
                                            DIM, DIM, 0, 0, 0, 0, 1.0f);
    gemm_mma<0, false><<<gp, 128, SM_STD>>>(Xp, Wkp, bk, nullptr, K, nullptr,
                                            DIM, DIM, 0, 0, 0, 0, 1.0f);
    gemm_mma<0, false><<<gp, 128, SM_STD>>>(Xp, Wvp, bv, nullptr, V, nullptr,
                                            DIM, DIM, 0, 0, 0, 0, 1.0f);

    // 3) E = exp(Q K^T / 32) -> fp16, per batch (softmax numerator)
    dim3 gs(SEQ / BN, SEQ / BM, NB);
    gemm_mma<3, false><<<gs, 128, SM_STD>>>(Q, K, nullptr, nullptr, E, nullptr,
                                            SEQ, DIM, 0,
                                            (size_t)SEQ * DIM, (size_t)SEQ * DIM,
                                            (size_t)SEQ * SEQ, EXP_SCALE);

    // 4) row sums of E (denominator)
    rowsum_kernel<<<MTOT, 256>>>(E, RS);

    // 5) out = (E * V) / rowsum   (B = V row-major, trans-loaded)
    dim3 go(DIM / BN, SEQ / BM, NB);
    gemm_mma<4, true><<<go, 128, SM_TRN>>>(E, V, nullptr, RS, nullptr, out,
                                           DIM, SEQ, DIM,
                                           (size_t)SEQ * SEQ, (size_t)SEQ * DIM,
                                           (size_t)SEQ * DIM, 1.0f);
}

// round 13
// speedup vs baseline: 7.7755x; 1.0386x over previous
#include <cuda_runtime.h>
#include <cuda_fp16.h>
#include <cstdint>
#include <cstddef>

#define NB  4
#define SEQ 4096
#define DIM 1024
#define MTOT (NB * SEQ)
#define NQKV 3072

// ---------------------------------------------------------------------------
// Scratch (static device globals; runtime allocation is forbidden)
// ---------------------------------------------------------------------------
__device__ __half g_X  [(size_t)MTOT * DIM];
__device__ __half g_W  [(size_t)NQKV * DIM];     // [Wq;Wk;Wv] rows
__device__ float  g_B3 [NQKV];                   // [bq;bk;bv]
__device__ __half g_QKV[(size_t)MTOT * NQKV];    // Q | K | V column blocks
__device__ __half g_E  [(size_t)NB * SEQ * SEQ]; // exp(scores), unnormalized
__device__ float  g_RS [(size_t)MTOT];           // row sums of E

// exp(x/32) = exp2(x * (1/32) * log2(e))
#define EXP_SCALE 0.045083183f

// ---------------------------------------------------------------------------
// PTX helpers
// ---------------------------------------------------------------------------
__device__ __forceinline__ uint32_t s2u(const void* p) {
    uint32_t a;
    asm("{ .reg .u64 t; cvta.to.shared.u64 t, %1; cvt.u32.u64 %0, t; }"
        : "=r"(a) : "l"(p));
    return a;
}
__device__ __forceinline__ void cpasync16(uint32_t s, const void* g) {
    asm volatile("cp.async.cg.shared.global [%0], [%1], 16;"
                 :: "r"(s), "l"(g) : "memory");
}
__device__ __forceinline__ void cp_commit() {
    asm volatile("cp.async.commit_group;" ::: "memory");
}
__device__ __forceinline__ void ldsm4(uint32_t& r0, uint32_t& r1,
                                      uint32_t& r2, uint32_t& r3, uint32_t a) {
    asm volatile("ldmatrix.sync.aligned.m8n8.x4.shared.b16 {%0,%1,%2,%3}, [%4];"
                 : "=r"(r0), "=r"(r1), "=r"(r2), "=r"(r3) : "r"(a));
}
__device__ __forceinline__ void ldsm4t(uint32_t& r0, uint32_t& r1,
                                       uint32_t& r2, uint32_t& r3, uint32_t a) {
    asm volatile("ldmatrix.sync.aligned.m8n8.x4.trans.shared.b16 {%0,%1,%2,%3}, [%4];"
                 : "=r"(r0), "=r"(r1), "=r"(r2), "=r"(r3) : "r"(a));
}
__device__ __forceinline__ void mma16816(float* c, const uint32_t* a,
                                         const uint32_t* b) {
    asm volatile(
        "mma.sync.aligned.m16n8k16.row.col.f32.f16.f16.f32 "
        "{%0,%1,%2,%3}, {%4,%5,%6,%7}, {%8,%9}, {%0,%1,%2,%3};"
        : "+f"(c[0]), "+f"(c[1]), "+f"(c[2]), "+f"(c[3])
        : "r"(a[0]), "r"(a[1]), "r"(a[2]), "r"(a[3]), "r"(b[0]), "r"(b[1]));
}
__device__ __forceinline__ uint32_t pr2h(__half a, __half b) {
    return ((uint32_t)__half_as_ushort(b) << 16) | __half_as_ushort(a);
}

// ---------------------------------------------------------------------------
// fp16 GEMM:  C[M,N] = A[M,K] * op(B)
// BTRANS=false: B rows are N-indexed, K contiguous (C = A*B^T).
// BTRANS=true : B rows are K-indexed, N contiguous (C = A*B), ldmatrix.trans.
// 256 threads (8 warps, 4x2), CTA tile 128x128, K slab 64, warp tile 32x64.
// cp.async 3-stage pipeline, 2 CTAs/SM -> 16 warps/SM (4 per SMSP).
// lda/ldb = global row strides (decoupled from N/K for the packed QKV matrix).
// EPI 0: +bias -> fp16.
// EPI 3: exp2(acc*alpha) -> fp16           (scores; softmax numerator)
// EPI 4: acc * (1/RS[row]) -> fp32         (A*V with fused normalization)
// ---------------------------------------------------------------------------
constexpr int BM = 128, BN = 128, BK = 64;
constexpr int PITCH_A  = 144;               // 128 B data + 16 pad
constexpr int ARR_A    = 128 * PITCH_A;     // 18432
constexpr int PITCH_BT = 272;               // 256 B data + 16 pad
constexpr int ARR_BT   = 64 * PITCH_BT;     // 17408
constexpr int SM_STD = 3 * (ARR_A + ARR_A);   // 110592
constexpr int SM_TRN = 3 * (ARR_A + ARR_BT);  // 107520

template <int EPI, bool BTRANS>
__global__ void __launch_bounds__(256, 2)
gemm_mma(const __half* __restrict__ Ag, const __half* __restrict__ Bg,
         const float* __restrict__ bias, const float* __restrict__ RS,
         __half* __restrict__ Ch, float* __restrict__ Cf,
         int N, int K, int lda, int ldb,
         size_t sA, size_t sB, size_t sC, float alpha)
{
    constexpr int ARRB  = BTRANS ? ARR_BT : ARR_A;
    constexpr int STAGE = ARR_A + ARRB;

    extern __shared__ char smem[];
    const int tid  = threadIdx.x;
    const int lane = tid & 31, warp = tid >> 5;
    const int wm = warp >> 1, wn = warp & 1;     // 4x2 grid of 32x64 tiles
    const int m0 = blockIdx.y * BM, n0 = blockIdx.x * BN;
    const size_t zb = blockIdx.z;

    const __half* A = Ag + zb * sA;
    const __half* B = Bg + zb * sB;
    const uint32_t sbase = s2u(smem);

    // ---- cp.async per-thread bases (4 slots each for A and B) ----
    const __half* gA = A + (size_t)(m0 + (tid >> 3)) * lda + (tid & 7) * 8;
    const uint32_t sA0 = (tid >> 3) * PITCH_A + (tid & 7) * 16;
    const __half* gB;
    uint32_t sB0;
    if (BTRANS) {
        gB  = B + (size_t)(tid >> 4) * ldb + n0 + (tid & 15) * 8;
        sB0 = (tid >> 4) * PITCH_BT + (tid & 15) * 16;
    } else {
        gB  = B + (size_t)(n0 + (tid >> 3)) * ldb + (tid & 7) * 8;
        sB0 = (tid >> 3) * PITCH_A + (tid & 7) * 16;
    }

    const int NS = K / BK;

    auto issue = [&](int slab) {
        const uint32_t st = sbase + (slab % 3) * STAGE;
        const __half* ga = gA + (size_t)slab * BK;
#pragma unroll
        for (int j = 0; j < 4; j++)
            cpasync16(st + sA0 + j * (32 * PITCH_A), ga + (size_t)j * 32 * lda);
        if (BTRANS) {
            const __half* gb = gB + (size_t)slab * BK * ldb;
#pragma unroll
            for (int j = 0; j < 4; j++)
                cpasync16(st + ARR_A + sB0 + j * (16 * PITCH_BT),
                          gb + (size_t)j * 16 * ldb);
        } else {
            const __half* gb = gB + (size_t)slab * BK;
#pragma unroll
            for (int j = 0; j < 4; j++)
                cpasync16(st + ARR_A + sB0 + j * (32 * PITCH_A),
                          gb + (size_t)j * 32 * ldb);
        }
    };

    issue(0); cp_commit();
    issue(1); cp_commit();

    float acc[2][8][4];
#pragma unroll
    for (int t = 0; t < 2; t++)
#pragma unroll
        for (int nt = 0; nt < 8; nt++)
#pragma unroll
            for (int f = 0; f < 4; f++) acc[t][nt][f] = 0.0f;

    const uint32_t aoff = (uint32_t)((wm * 32 + (lane & 15)) * PITCH_A +
                                     ((lane >> 4) << 4));
    uint32_t boff;
    if (BTRANS)
        boff = (uint32_t)(((((lane >> 3) & 1) << 3) + (lane & 7)) * PITCH_BT +
                          ((lane >> 4) << 4) + wn * 128);
    else
        boff = (uint32_t)((wn * 64 + ((lane >> 4) << 3) + (lane & 7)) * PITCH_A +
                          (((lane >> 3) & 1) << 4));

    for (int s = 0; s < NS; s++) {
        asm volatile("cp.async.wait_group 1;" ::: "memory");
        __syncthreads();
        if (s + 2 < NS) issue(s + 2);
        cp_commit();

        const uint32_t st = sbase + (s % 3) * STAGE;
#pragma unroll
        for (int kk = 0; kk < 4; kk++) {
            uint32_t bh[16];
#pragma unroll
            for (int p = 0; p < 4; p++) {
                if (BTRANS)
                    ldsm4t(bh[4*p], bh[4*p+1], bh[4*p+2], bh[4*p+3],
                           st + ARR_A + boff + kk * (16 * PITCH_BT) + p * 32);
                else
                    ldsm4(bh[4*p], bh[4*p+1], bh[4*p+2], bh[4*p+3],
                          st + ARR_A + boff + kk * 32 + p * (16 * PITCH_A));
            }
#pragma unroll
            for (int t = 0; t < 2; t++) {
                uint32_t ah[4];
                ldsm4(ah[0], ah[1], ah[2], ah[3],
                      st + aoff + t * (16 * PITCH_A) + kk * 32);
#pragma unroll
                for (int nt = 0; nt < 8; nt++)
                    mma16816(acc[t][nt], ah, &bh[2 * nt]);
            }
        }
        __syncthreads();
    }
    asm volatile("cp.async.wait_group 0;" ::: "memory");

    // ---- EPI 4: stage reciprocal row sums through (now idle) smem ----
    float* srs = (float*)smem;
    if (EPI == 4) {
        __syncthreads();
        if (tid < 128)
            srs[tid] = 1.0f / RS[zb * SEQ + m0 + tid];
        __syncthreads();
    }

    // ---- epilogue ----
    const int mrow = lane >> 2;
    const int ncol = (lane & 3) * 2;
#pragma unroll
    for (int t = 0; t < 2; t++)
#pragma unroll
        for (int nt = 0; nt < 8; nt++)
#pragma unroll
            for (int hp = 0; hp < 2; hp++) {
                int ml = wm * 32 + t * 16 + mrow + hp * 8;   // row within CTA
                int m = m0 + ml;
                int n = n0 + wn * 64 + nt * 8 + ncol;
                float v0 = acc[t][nt][hp * 2 + 0];
                float v1 = acc[t][nt][hp * 2 + 1];
                size_t off = zb * sC + (size_t)m * N + n;
                if (EPI == 0) {
                    v0 += bias[n]; v1 += bias[n + 1];
                    *(uint32_t*)(Ch + off) = pr2h(__float2half(v0), __float2half(v1));
                } else if (EPI == 3) {
                    float e0 = exp2f(v0 * alpha);
                    float e1 = exp2f(v1 * alpha);
                    *(uint32_t*)(Ch + off) = pr2h(__float2half(e0), __float2half(e1));
                } else {
                    float inv = srs[ml];
                    *(float2*)(Cf + off) = make_float2(v0 * inv, v1 * inv);
                }
            }
}

// ---------------------------------------------------------------------------
// fp32 -> fp16 convert, float4-vectorized (X)
// ---------------------------------------------------------------------------
__global__ void conv_kernel(const float* __restrict__ x,
                            __half* __restrict__ h, size_t n4)
{
    size_t i  = (size_t)blockIdx.x * blockDim.x + threadIdx.x;
    size_t st = (size_t)gridDim.x * blockDim.x;
    for (; i < n4; i += st) {
        float4 v = ((const float4*)x)[i];
        ((uint2*)h)[i] = make_uint2(
            pr2h(__float2half(v.x), __float2half(v.y)),
            pr2h(__float2half(v.z), __float2half(v.w)));
    }
}

// Concatenate 3 weight matrices -> g_W (fp16) and 3 biases -> g_B3 (fp32).
__global__ void conv3_kernel(const float* __restrict__ w0,
                             const float* __restrict__ w1,
                             const float* __restrict__ w2,
                             const float* __restrict__ b0,
                             const float* __restrict__ b1,
                             const float* __restrict__ b2,
                             __half* __restrict__ W, float* __restrict__ B3,
                             size_t n4)
{
    const float* x = (blockIdx.y == 0) ? w0 : (blockIdx.y == 1) ? w1 : w2;
    __half*      h = W + (size_t)blockIdx.y * DIM * DIM;
    size_t i  = (size_t)blockIdx.x * blockDim.x + threadIdx.x;
    size_t st = (size_t)gridDim.x * blockDim.x;
    for (; i < n4; i += st) {
        float4 v = ((const float4*)x)[i];
        ((uint2*)h)[i] = make_uint2(
            pr2h(__float2half(v.x), __float2half(v.y)),
            pr2h(__float2half(v.z), __float2half(v.w)));
    }
    if (blockIdx.x == 0) {
        const float* b = (blockIdx.y == 0) ? b0 : (blockIdx.y == 1) ? b1 : b2;
        for (int j = threadIdx.x; j < DIM; j += blockDim.x)
            B3[blockIdx.y * DIM + j] = b[j];
    }
}

// ---------------------------------------------------------------------------
// Row sums of E: one block per row, deterministic fixed-order reduction.
// ---------------------------------------------------------------------------
__global__ void __launch_bounds__(256)
rowsum_kernel(const __half* __restrict__ E, float* __restrict__ RS)
{
    const __half2* p2 = (const __half2*)(E + (size_t)blockIdx.x * SEQ);
    const int t = threadIdx.x;

    float sum = 0.0f;
#pragma unroll
    for (int i = 0; i < 8; i++) {
        float2 v = __half22float2(p2[t + 256 * i]);
        sum += v.x + v.y;
    }
    __shared__ float red[8];
#pragma unroll
    for (int o = 16; o > 0; o >>= 1)
        sum += __shfl_xor_sync(0xffffffffu, sum, o);
    if ((t & 31) == 0) red[t >> 5] = sum;
    __syncthreads();
    if (t == 0) {
        float s = 0.0f;
#pragma unroll
        for (int w = 0; w < 8; w++) s += red[w];
        RS[blockIdx.x] = s;
    }
}

// ---------------------------------------------------------------------------
extern "C" void kernel_launch(void* const* d_in, const int* in_sizes, int n_in,
                              void* d_out, int out_size)
{
    const float* X  = (const float*)d_in[0];
    const float* Wq = (const float*)d_in[1];
    const float* bq = (const float*)d_in[2];
    const float* Wk = (const float*)d_in[3];
    const float* bk = (const float*)d_in[4];
    const float* Wv = (const float*)d_in[5];
    const float* bv = (const float*)d_in[6];
    float* out = (float*)d_out;

    __half *Xp, *W, *QKV, *E;
    float *B3, *RS;
    cudaGetSymbolAddress((void**)&Xp,  g_X);
    cudaGetSymbolAddress((void**)&W,   g_W);
    cudaGetSymbolAddress((void**)&B3,  g_B3);
    cudaGetSymbolAddress((void**)&QKV, g_QKV);
    cudaGetSymbolAddress((void**)&E,   g_E);
    cudaGetSymbolAddress((void**)&RS,  g_RS);

    cudaFuncSetAttribute(gemm_mma<0, false>, cudaFuncAttributeMaxDynamicSharedMemorySize, SM_STD);
    cudaFuncSetAttribute(gemm_mma<3, false>, cudaFuncAttributeMaxDynamicSharedMemorySize, SM_STD);
    cudaFuncSetAttribute(gemm_mma<4, true>,  cudaFuncAttributeMaxDynamicSharedMemorySize, SM_TRN);

    // 1) operand prep -> fp16 (X; concatenated W + bias)
    conv_kernel<<<2048, 256>>>(X, Xp, (size_t)MTOT * DIM / 4);
    dim3 gw(512, 3);
    conv3_kernel<<<gw, 256>>>(Wq, Wk, Wv, bq, bk, bv, W, B3, (size_t)DIM * DIM / 4);

    // 2) fused projections: QKV[m, 0:3072] = X*[Wq;Wk;Wv]^T + [bq;bk;bv]
    dim3 gp(NQKV / BN, MTOT / BM, 1);
    gemm_mma<0, false><<<gp, 256, SM_STD>>>(Xp, W, B3, nullptr, QKV, nullptr,
                                            NQKV, DIM, DIM, DIM, 0, 0, 0, 1.0f);

    // 3) E = exp(Q K^T / 32) -> fp16, per batch
    dim3 gs(SEQ / BN, SEQ / BM, NB);
    gemm_mma<3, false><<<gs, 256, SM_STD>>>(QKV, QKV + DIM, nullptr, nullptr, E, nullptr,
                                            SEQ, DIM, NQKV, NQKV,
                                            (size_t)SEQ * NQKV, (size_t)SEQ * NQKV,
                                            (size_t)SEQ * SEQ, EXP_SCALE);

    // 4) row sums of E (softmax denominator)
    rowsum_kernel<<<MTOT, 256>>>(E, RS);

    // 5) out = (E * V) / rowsum   (V = QKV cols 2048:3072, row-major, trans-loaded)
    dim3 go(DIM / BN, SEQ / BM, NB);
    gemm_mma<4, true><<<go, 256, SM_TRN>>>(E, QKV + 2 * DIM, nullptr, RS, nullptr, out,
                                           DIM, SEQ, SEQ, NQKV,
                                           (size_t)SEQ * SEQ, (size_t)SEQ * NQKV,
                                           (size_t)SEQ * DIM, 1.0f);
}